// round 13
// baseline (speedup 1.0000x reference)
#include <cuda_runtime.h>
#include <cuda_bf16.h>
#include <math.h>
#include <stdint.h>

#define B_SZ   64
#define FULLN  513
#define E_SZ   768
#define NB     32
#define GRIDSZ 8
#define NHEAD  12
#define HDIM   64
#define NP     (B_SZ * NB)      // 2048

// ---------------- scratch (device globals) ----------------
__device__ float g_S  [NP * E_SZ];
__device__ float g_T  [E_SZ * E_SZ];
__device__ float g_WS [E_SZ * E_SZ];
__device__ float g_P1 [4 * B_SZ * E_SZ];
__device__ float g_P2 [12 * 4 * 64 * 64];
__device__ float g_PB [2 * E_SZ * E_SZ];
__device__ float g_WsT[E_SZ * E_SZ];
__device__ float g_WkT[E_SZ * E_SZ];

// ================= tensor-core helpers =================
__device__ __forceinline__ uint32_t smem_u32(const void* p) {
    uint32_t a;
    asm("{ .reg .u64 t; cvta.to.shared.u64 t, %1; cvt.u32.u64 %0, t; }" : "=r"(a) : "l"(p));
    return a;
}
__device__ __forceinline__ void ldsm4(uint32_t* r, uint32_t addr) {
    asm volatile("ldmatrix.sync.aligned.m8n8.x4.shared.b16 {%0,%1,%2,%3}, [%4];"
        : "=r"(r[0]), "=r"(r[1]), "=r"(r[2]), "=r"(r[3]) : "r"(addr));
}
__device__ __forceinline__ void mma16816(float* d, const uint32_t* a, const uint32_t* b) {
    asm volatile("mma.sync.aligned.m16n8k16.row.col.f32.bf16.bf16.f32 "
        "{%0,%1,%2,%3}, {%4,%5,%6,%7}, {%8,%9}, {%0,%1,%2,%3};"
        : "+f"(d[0]), "+f"(d[1]), "+f"(d[2]), "+f"(d[3])
        : "r"(a[0]), "r"(a[1]), "r"(a[2]), "r"(a[3]), "r"(b[0]), "r"(b[1]));
}
__device__ __forceinline__ void cvt_hl(float4 v, uint2& hi, uint2& lo) {
    __nv_bfloat16 h0 = __float2bfloat16(v.x), h1 = __float2bfloat16(v.y);
    __nv_bfloat16 h2 = __float2bfloat16(v.z), h3 = __float2bfloat16(v.w);
    __nv_bfloat16 l0 = __float2bfloat16(v.x - __bfloat162float(h0));
    __nv_bfloat16 l1 = __float2bfloat16(v.y - __bfloat162float(h1));
    __nv_bfloat16 l2 = __float2bfloat16(v.z - __bfloat162float(h2));
    __nv_bfloat16 l3 = __float2bfloat16(v.w - __bfloat162float(h3));
    __nv_bfloat162 hp0 = __halves2bfloat162(h0, h1), hp1 = __halves2bfloat162(h2, h3);
    __nv_bfloat162 lp0 = __halves2bfloat162(l0, l1), lp1 = __halves2bfloat162(l2, l3);
    hi = make_uint2(*(uint32_t*)&hp0, *(uint32_t*)&hp1);
    lo = make_uint2(*(uint32_t*)&lp0, *(uint32_t*)&lp1);
}

#define PITCH   144
#define A_H_OFF 0
#define A_L_OFF 9216
#define B_H_OFF 18432
#define B_L_OFF 27648
#define TILE_SMEM 36864

__device__ __forceinline__ void store_pair(char* sm, int base_h, int base_l,
                                           int row, int c4, float4 v) {
    uint2 hi, lo;
    cvt_hl(v, hi, lo);
    *(uint2*)(sm + base_h + row * PITCH + c4 * 8) = hi;
    *(uint2*)(sm + base_l + row * PITCH + c4 * 8) = lo;
}

// 64-K tile compute, 8 warps: warp tile 16x32.
__device__ __forceinline__ void mma_tile64_8w(uint32_t sb, int wm, int wn, int lane,
                                              float acc[4][4]) {
    #pragma unroll
    for (int ks = 0; ks < 4; ks++) {
        uint32_t a_h[4], a_l[4], b_h[4][2], b_l[4][2];
        {
            uint32_t r  = wm + (lane & 15);
            uint32_t cb = ks * 32 + ((lane >> 4) << 4);
            ldsm4(a_h, sb + A_H_OFF + r * PITCH + cb);
            ldsm4(a_l, sb + A_L_OFF + r * PITCH + cb);
        }
        #pragma unroll
        for (int g = 0; g < 2; g++) {
            uint32_t n  = wn + g * 16 + (lane & 7) + (((lane >> 4) & 1) << 3);
            uint32_t cb = ks * 32 + (((lane >> 3) & 1) << 4);
            uint32_t t[4];
            ldsm4(t, sb + B_H_OFF + n * PITCH + cb);
            b_h[g*2][0] = t[0]; b_h[g*2][1] = t[1];
            b_h[g*2+1][0] = t[2]; b_h[g*2+1][1] = t[3];
            ldsm4(t, sb + B_L_OFF + n * PITCH + cb);
            b_l[g*2][0] = t[0]; b_l[g*2][1] = t[1];
            b_l[g*2+1][0] = t[2]; b_l[g*2+1][1] = t[3];
        }
        #pragma unroll
        for (int ni = 0; ni < 4; ni++) {
            mma16816(acc[ni], a_h, b_h[ni]);
            mma16816(acc[ni], a_h, b_l[ni]);
            mma16816(acc[ni], a_l, b_h[ni]);
        }
    }
}

// generic NT tile GEMM core (64x64 CTA tile)
__device__ __forceinline__ void hmma_tile_core(
    char* sm, uint32_t sb, int tid,
    const float* __restrict__ A, const float* __restrict__ B,
    const float* __restrict__ bias, float* __restrict__ Cp,
    int bm, int bn, int kbase, int niter)
{
    const int wid = tid >> 5, lane = tid & 31;
    const int wm = (wid & 3) * 16, wn = (wid >> 2) * 32;

    float acc[4][4] = {};
    float4 pa[4], pb[4];
    #pragma unroll
    for (int j = 0; j < 4; j++) {
        int fid = tid + j * 256;
        int row = fid >> 4, c4 = fid & 15;
        pa[j] = *(const float4*)(A + (size_t)(bm + row) * E_SZ + kbase + c4 * 4);
        pb[j] = *(const float4*)(B + (size_t)(bn + row) * E_SZ + kbase + c4 * 4);
    }
    for (int it = 0; it < niter; it++) {
        #pragma unroll
        for (int j = 0; j < 4; j++) {
            int fid = tid + j * 256;
            int row = fid >> 4, c4 = fid & 15;
            store_pair(sm, A_H_OFF, A_L_OFF, row, c4, pa[j]);
            store_pair(sm, B_H_OFF, B_L_OFF, row, c4, pb[j]);
        }
        __syncthreads();
        if (it + 1 < niter) {
            int k0 = kbase + (it + 1) * 64;
            #pragma unroll
            for (int j = 0; j < 4; j++) {
                int fid = tid + j * 256;
                int row = fid >> 4, c4 = fid & 15;
                pa[j] = *(const float4*)(A + (size_t)(bm + row) * E_SZ + k0 + c4 * 4);
                pb[j] = *(const float4*)(B + (size_t)(bn + row) * E_SZ + k0 + c4 * 4);
            }
        }
        mma_tile64_8w(sb, wm, wn, lane, acc);
        __syncthreads();
    }
    {
        int r0 = bm + wm + (lane >> 2);
        #pragma unroll
        for (int ni = 0; ni < 4; ni++) {
            int c0 = bn + wn + ni * 8 + (lane & 3) * 2;
            float bb0 = bias ? bias[c0] : 0.f;
            float bb1 = bias ? bias[c0 + 1] : 0.f;
            *(float2*)(Cp + (size_t)r0 * E_SZ + c0) =
                make_float2(acc[ni][0] + bb0, acc[ni][1] + bb1);
            *(float2*)(Cp + (size_t)(r0 + 8) * E_SZ + c0) =
                make_float2(acc[ni][2] + bb0, acc[ni][3] + bb1);
        }
    }
}

// ---------------------------------------------------------------
// gather one (b,p) point; 192 active lanes of a 256-thread block
// ---------------------------------------------------------------
__device__ __forceinline__ void gather_point(
    int bp, int t,
    const float* __restrict__ x,
    const float* __restrict__ bc,
    const float* __restrict__ off,
    float* __restrict__ S)
{
    if (t >= 192) return;
    const int b = bp >> 5, p = bp & 31;

    float cx = fminf(fmaxf(bc[p*3+0] + off[bp*3+0], -1.f), 1.f);
    float cy = fminf(fmaxf(bc[p*3+1] + off[bp*3+1], -1.f), 1.f);
    float cz = fminf(fmaxf(bc[p*3+2] + off[bp*3+2], -1.f), 1.f);

    float ix = (cx + 1.0f) * 0.5f * (GRIDSZ - 1);
    float iy = (cy + 1.0f) * 0.5f * (GRIDSZ - 1);
    float iz = (cz + 1.0f) * 0.5f * (GRIDSZ - 1);

    float fx = floorf(ix), fy = floorf(iy), fz = floorf(iz);
    float wx = ix - fx, wy = iy - fy, wz = iz - fz;

    int x0 = min(max((int)fx, 0), GRIDSZ-1);
    int y0 = min(max((int)fy, 0), GRIDSZ-1);
    int z0 = min(max((int)fz, 0), GRIDSZ-1);
    int x1 = min(x0 + 1, GRIDSZ-1);
    int y1 = min(y0 + 1, GRIDSZ-1);
    int z1 = min(z0 + 1, GRIDSZ-1);

    const float* xb = x + ((size_t)b * FULLN + 1) * E_SZ;

    int idx[8];
    idx[0] = (((z0*GRIDSZ)+y0)*GRIDSZ + x0) * E_SZ;
    idx[1] = (((z0*GRIDSZ)+y0)*GRIDSZ + x1) * E_SZ;
    idx[2] = (((z0*GRIDSZ)+y1)*GRIDSZ + x0) * E_SZ;
    idx[3] = (((z0*GRIDSZ)+y1)*GRIDSZ + x1) * E_SZ;
    idx[4] = (((z1*GRIDSZ)+y0)*GRIDSZ + x0) * E_SZ;
    idx[5] = (((z1*GRIDSZ)+y0)*GRIDSZ + x1) * E_SZ;
    idx[6] = (((z1*GRIDSZ)+y1)*GRIDSZ + x0) * E_SZ;
    idx[7] = (((z1*GRIDSZ)+y1)*GRIDSZ + x1) * E_SZ;

    float w[8];
    w[0] = (1-wz)*(1-wy)*(1-wx);
    w[1] = (1-wz)*(1-wy)*wx;
    w[2] = (1-wz)*wy*(1-wx);
    w[3] = (1-wz)*wy*wx;
    w[4] = wz*(1-wy)*(1-wx);
    w[5] = wz*(1-wy)*wx;
    w[6] = wz*wy*(1-wx);
    w[7] = wz*wy*wx;

    float4* outv = (float4*)(S + (size_t)bp * E_SZ);
    float4 acc = make_float4(0.f,0.f,0.f,0.f);
    #pragma unroll
    for (int i = 0; i < 8; i++) {
        float4 v = ((const float4*)(xb + idx[i]))[t];
        acc.x = fmaf(w[i], v.x, acc.x);
        acc.y = fmaf(w[i], v.y, acc.y);
        acc.z = fmaf(w[i], v.z, acc.z);
        acc.w = fmaf(w[i], v.w, acc.w);
    }
    outv[t] = acc;
}

// ---------------------------------------------------------------
// k1: qproj (48) | transposes (1152)
// ---------------------------------------------------------------
#define K1_QPROJ 48
#define K1_GRID  (K1_QPROJ + 1152)

__global__ __launch_bounds__(256)
void k1_front(const float* __restrict__ bio,
              const float* __restrict__ in_proj_w,
              const float* __restrict__ sample_w,
              float* __restrict__ P1,
              float* __restrict__ WsT,
              float* __restrict__ WkT)
{
    __shared__ __align__(16) char sm[TILE_SMEM];
    const int bid = blockIdx.x;
    const int t   = threadIdx.x;

    if (bid < K1_QPROJ) {
        const int n = bid % 12, z = bid / 12;
        hmma_tile_core(sm, smem_u32(sm), t, bio, in_proj_w, nullptr,
                       P1 + (size_t)z * B_SZ * E_SZ, 0, n * 64, z * 192, 3);
    } else {
        int tb = bid - K1_QPROJ;
        const int zsel = tb / 576; tb -= zsel * 576;
        const int bx = (tb % 24) * 32, by = (tb / 24) * 32;
        const float* A = zsel ? (in_proj_w + (size_t)E_SZ * E_SZ) : sample_w;
        float* At      = zsel ? WkT : WsT;
        float (*ts)[33] = (float(*)[33])sm;
        const int tx = t & 31, ty = t >> 5;
        #pragma unroll
        for (int i = 0; i < 32; i += 8)
            ts[ty + i][tx] = A[(size_t)(by + ty + i) * E_SZ + bx + tx];
        __syncthreads();
        #pragma unroll
        for (int i = 0; i < 32; i += 8)
            At[(size_t)(bx + ty + i) * E_SZ + by + tx] = ts[tx][ty + i];
    }
}

// ---------------------------------------------------------------
// k2: thead (144) | gather half 1 (1024)
// ---------------------------------------------------------------
#define K2_THEAD 144
#define K2_GRID  (K2_THEAD + 1024)

__global__ __launch_bounds__(256)
void k2_thead_gather(const float* __restrict__ P1,
                     const float* __restrict__ in_proj_b,
                     const float* __restrict__ WkT,
                     float* __restrict__ T,
                     const float* __restrict__ x,
                     const float* __restrict__ bc,
                     const float* __restrict__ off,
                     float* __restrict__ S)
{
    __shared__ __align__(16) char sm[TILE_SMEM];
    const int bid = blockIdx.x;
    const int tid = threadIdx.x;

    if (bid >= K2_THEAD) {
        gather_point(bid - K2_THEAD, tid, x, bc, off, S);
        return;
    }

    const int wid  = tid >> 5, lane = tid & 31;
    const int e0   = (bid % 12) * 64;
    const int h    = bid / 12;
    const int wm   = (wid & 3) * 16, wn = (wid >> 2) * 32;
    const uint32_t sb = smem_u32(sm);

    #pragma unroll
    for (int j = 0; j < 4; j++) {
        int fid = tid + j * 256;
        int row = fid >> 4, c4 = fid & 15;
        const float* pbase = P1 + (size_t)row * E_SZ + h * 64 + c4 * 4;
        float4 v = *(const float4*)pbase;
        #pragma unroll
        for (int s = 1; s < 4; s++) {
            float4 p = *(const float4*)(pbase + (size_t)s * B_SZ * E_SZ);
            v.x += p.x; v.y += p.y; v.z += p.z; v.w += p.w;
        }
        float4 bq = *(const float4*)(in_proj_b + h * 64 + c4 * 4);
        v.x += bq.x; v.y += bq.y; v.z += bq.z; v.w += bq.w;
        store_pair(sm, A_H_OFF, A_L_OFF, row, c4, v);
        float4 vb = *(const float4*)(WkT + (size_t)(e0 + row) * E_SZ + h * 64 + c4 * 4);
        store_pair(sm, B_H_OFF, B_L_OFF, row, c4, vb);
    }
    __syncthreads();

    float acc[4][4] = {};
    mma_tile64_8w(sb, wm, wn, lane, acc);

    {
        int r0 = h * 64 + wm + (lane >> 2);
        #pragma unroll
        for (int ni = 0; ni < 4; ni++) {
            int c0 = e0 + wn + ni * 8 + (lane & 3) * 2;
            *(float2*)(T + (size_t)r0 * E_SZ + c0) = make_float2(acc[ni][0], acc[ni][1]);
            *(float2*)(T + (size_t)(r0 + 8) * E_SZ + c0) = make_float2(acc[ni][2], acc[ni][3]);
        }
    }
}

// ---------------------------------------------------------------
// Big NT GEMM body, CTA tile 128x64 (8 warps, warp tile 32x32)
// ---------------------------------------------------------------
#define BG_A_H 0
#define BG_A_L 18432
#define BG_B_H 36864
#define BG_B_L 46080
#define BG_SMEM 55296

__device__ __forceinline__ void big_nt_body(
    char* sm, int tid,
    const float* __restrict__ A, const float* __restrict__ B,
    float* __restrict__ PB, int bm, int bn, int z)
{
    const int wid = tid >> 5, lane = tid & 31;
    const int wm = (wid & 3) * 32, wn = (wid >> 2) * 32;
    const int kbase = z * 384;
    const uint32_t sb = smem_u32(sm);

    float acc[2][4][4] = {};
    float4 pa[8], pb[4];

    #pragma unroll
    for (int j = 0; j < 8; j++) {
        int fid = tid + j * 256;
        int row = fid >> 4, c4 = fid & 15;
        pa[j] = *(const float4*)(A + (size_t)(bm + row) * E_SZ + kbase + c4 * 4);
    }
    #pragma unroll
    for (int j = 0; j < 4; j++) {
        int fid = tid + j * 256;
        int row = fid >> 4, c4 = fid & 15;
        pb[j] = *(const float4*)(B + (size_t)(bn + row) * E_SZ + kbase + c4 * 4);
    }

    for (int it = 0; it < 6; it++) {
        #pragma unroll
        for (int j = 0; j < 8; j++) {
            int fid = tid + j * 256;
            int row = fid >> 4, c4 = fid & 15;
            store_pair(sm, BG_A_H, BG_A_L, row, c4, pa[j]);
        }
        #pragma unroll
        for (int j = 0; j < 4; j++) {
            int fid = tid + j * 256;
            int row = fid >> 4, c4 = fid & 15;
            store_pair(sm, BG_B_H, BG_B_L, row, c4, pb[j]);
        }
        __syncthreads();
        if (it + 1 < 6) {
            int k0 = kbase + (it + 1) * 64;
            #pragma unroll
            for (int j = 0; j < 8; j++) {
                int fid = tid + j * 256;
                int row = fid >> 4, c4 = fid & 15;
                pa[j] = *(const float4*)(A + (size_t)(bm + row) * E_SZ + k0 + c4 * 4);
            }
            #pragma unroll
            for (int j = 0; j < 4; j++) {
                int fid = tid + j * 256;
                int row = fid >> 4, c4 = fid & 15;
                pb[j] = *(const float4*)(B + (size_t)(bn + row) * E_SZ + k0 + c4 * 4);
            }
        }
        #pragma unroll
        for (int ks = 0; ks < 4; ks++) {
            uint32_t a_h[2][4], a_l[2][4], b_h[4][2], b_l[4][2];
            #pragma unroll
            for (int mi = 0; mi < 2; mi++) {
                uint32_t r  = wm + mi * 16 + (lane & 15);
                uint32_t cb = ks * 32 + ((lane >> 4) << 4);
                ldsm4(a_h[mi], sb + BG_A_H + r * PITCH + cb);
                ldsm4(a_l[mi], sb + BG_A_L + r * PITCH + cb);
            }
            #pragma unroll
            for (int g = 0; g < 2; g++) {
                uint32_t n  = wn + g * 16 + (lane & 7) + (((lane >> 4) & 1) << 3);
                uint32_t cb = ks * 32 + (((lane >> 3) & 1) << 4);
                uint32_t t[4];
                ldsm4(t, sb + BG_B_H + n * PITCH + cb);
                b_h[g*2][0] = t[0]; b_h[g*2][1] = t[1];
                b_h[g*2+1][0] = t[2]; b_h[g*2+1][1] = t[3];
                ldsm4(t, sb + BG_B_L + n * PITCH + cb);
                b_l[g*2][0] = t[0]; b_l[g*2][1] = t[1];
                b_l[g*2+1][0] = t[2]; b_l[g*2+1][1] = t[3];
            }
            #pragma unroll
            for (int mi = 0; mi < 2; mi++)
                #pragma unroll
                for (int ni = 0; ni < 4; ni++) {
                    mma16816(acc[mi][ni], a_h[mi], b_h[ni]);
                    mma16816(acc[mi][ni], a_h[mi], b_l[ni]);
                    mma16816(acc[mi][ni], a_l[mi], b_h[ni]);
                }
        }
        __syncthreads();
    }

    float* Cp = PB + (size_t)z * E_SZ * E_SZ;
    #pragma unroll
    for (int mi = 0; mi < 2; mi++) {
        int r0 = bm + wm + mi * 16 + (lane >> 2);
        #pragma unroll
        for (int ni = 0; ni < 4; ni++) {
            int c0 = bn + wn + ni * 8 + (lane & 3) * 2;
            *(float2*)(Cp + (size_t)r0 * E_SZ + c0) =
                make_float2(acc[mi][ni][0], acc[mi][ni][1]);
            *(float2*)(Cp + (size_t)(r0 + 8) * E_SZ + c0) =
                make_float2(acc[mi][ni][2], acc[mi][ni][3]);
        }
    }
}

// ---------------------------------------------------------------
// k3: gemm1 (144 flattened) | gather half 2 (1024)
// ---------------------------------------------------------------
#define K3_GEMM 144
#define K3_GRID (K3_GEMM + 1024)

__global__ __launch_bounds__(256)
void k3_gemm1_gather(const float* __restrict__ T,
                     const float* __restrict__ WsT,
                     float* __restrict__ PB,
                     const float* __restrict__ x,
                     const float* __restrict__ bc,
                     const float* __restrict__ off,
                     float* __restrict__ S)
{
    __shared__ __align__(16) char sm[BG_SMEM];
    const int bid = blockIdx.x;
    const int tid = threadIdx.x;

    if (bid >= K3_GEMM) {
        gather_point(1024 + (bid - K3_GEMM), tid, x, bc, off, S);
        return;
    }
    const int n = bid % 12;
    const int rest = bid / 12;
    const int m = rest % 6, z = rest / 6;
    big_nt_body(sm, tid, T, WsT, PB, m * 128, n * 64, z);
}

// gemm2: plain big NT (grid (12,6,2))
__global__ __launch_bounds__(256)
void hmma_nt_split(const float* __restrict__ A,
                   const float* __restrict__ B,
                   float* __restrict__ PB)
{
    __shared__ __align__(16) char sm[BG_SMEM];
    big_nt_body(sm, threadIdx.x, A, B, PB,
                blockIdx.y * 128, blockIdx.x * 64, blockIdx.z);
}

// ---------------------------------------------------------------
// Fused attention: ONE CTA per batch (all 12 heads), 512 thr.
// smem: S (32x768) + q (12x768) + sc/at = 138240 B
// ---------------------------------------------------------------
__global__ __launch_bounds__(512)
void attn_fuse_kernel(const float* __restrict__ QHp,
                      const float* __restrict__ S,
                      float* __restrict__ WS)
{
    extern __shared__ float smf[];
    float* Ssm = smf;                          // 32*768
    float* qsm = smf + NB * E_SZ;              // 12*768
    float* sc  = qsm + NHEAD * E_SZ;           // 12*32
    float* at  = sc + NHEAD * NB;              // 12*32

    const int b  = blockIdx.x;
    const int t  = threadIdx.x;
    const int w = t >> 5, lane = t & 31;

    // stage 0: S tile + all 12 q rows (partials summed)
    {
        const float4* src = (const float4*)(S + (size_t)b * NB * E_SZ);
        float4* dst = (float4*)Ssm;
        #pragma unroll
        for (int i = t; i < NB * E_SZ / 4; i += 512) dst[i] = src[i];
        float4* qdst = (float4*)qsm;
        for (int i = t; i < NHEAD * E_SZ / 4; i += 512) {
            int hl = i / 192, c4 = i - hl * 192;
            const float4* q0 = (const float4*)(QHp + (size_t)(hl * 64 + b) * E_SZ) + c4;
            float4 v0 = *q0;
            float4 v1 = *(const float4*)((const float*)q0 + (size_t)E_SZ * E_SZ);
            v0.x += v1.x; v0.y += v1.y; v0.z += v1.z; v0.w += v1.w;
            qdst[i] = v0;
        }
    }
    __syncthreads();

    // stage 2: scores. 12 warps = 6 head-pairs x 2 p-halves(16).
    if (w < 12) {
        const int hp = w >> 1, pg = w & 1;
        const int ha = hp * 2, hb = ha + 1;
        float qa[24], qb[24];
        #pragma unroll
        for (int i = 0; i < 24; i++) {
            qa[i] = qsm[ha * E_SZ + lane + i * 32];
            qb[i] = qsm[hb * E_SZ + lane + i * 32];
        }
        #pragma unroll
        for (int p = 0; p < 16; p++) {
            const int pp = pg * 16 + p;
            const float* sr = Ssm + pp * E_SZ;
            float acca = 0.f, accb = 0.f;
            #pragma unroll
            for (int i = 0; i < 24; i++) {
                float sv = sr[lane + i * 32];
                acca = fmaf(qa[i], sv, acca);
                accb = fmaf(qb[i], sv, accb);
            }
            #pragma unroll
            for (int o = 16; o; o >>= 1) {
                acca += __shfl_xor_sync(0xffffffffu, acca, o);
                accb += __shfl_xor_sync(0xffffffffu, accb, o);
            }
            if (lane == 0) {
                sc[ha * 32 + pp] = acca * 0.125f;
                sc[hb * 32 + pp] = accb * 0.125f;
            }
        }
    }
    __syncthreads();

    // stage 3: softmax per head (12 warps)
    if (w < NHEAD) {
        float s = sc[w*32 + lane];
        float m = s;
        #pragma unroll
        for (int o = 16; o; o >>= 1) m = fmaxf(m, __shfl_xor_sync(0xffffffffu, m, o));
        float e = __expf(s - m);
        float sum = e;
        #pragma unroll
        for (int o = 16; o; o >>= 1) sum += __shfl_xor_sync(0xffffffffu, sum, o);
        at[w*32 + lane] = e / sum;
    }
    __syncthreads();

    // stage 4: weighted S. 12 warps = 6 head-pairs x 2 c-halves(384).
    if (w < 12) {
        const int hp = w >> 1, cg = w & 1;
        const int ha = hp * 2, hb = ha + 1;
        float ata[32], atb[32];
        #pragma unroll
        for (int p = 0; p < 32; p++) {
            ata[p] = at[ha * 32 + p];
            atb[p] = at[hb * 32 + p];
        }
        float* wrow_a = WS + (size_t)(ha * 64 + b) * E_SZ;
        float* wrow_b = WS + (size_t)(hb * 64 + b) * E_SZ;
        #pragma unroll
        for (int j = 0; j < 12; j++) {
            const int c = cg * 384 + j * 32 + lane;
            float acca = 0.f, accb = 0.f;
            #pragma unroll
            for (int p = 0; p < 32; p++) {
                float sv = Ssm[p * E_SZ + c];
                acca = fmaf(ata[p], sv, acca);
                accb = fmaf(atb[p], sv, accb);
            }
            wrow_a[c] = acca;
            wrow_b[c] = accb;
        }
    }
}

// ---------------------------------------------------------------
// ctx HMMA: A = Up0 + Up1 + bs (fused), B = Wv_h. grid (1,12,4)
// ---------------------------------------------------------------
__global__ __launch_bounds__(256)
void ctx_hmma(const float* __restrict__ Up,
              const float* __restrict__ sample_b,
              const float* __restrict__ in_proj_w,
              float* __restrict__ P2)
{
    __shared__ __align__(16) char sm[TILE_SMEM];
    const int tid  = threadIdx.x;
    const int wid  = tid >> 5, lane = tid & 31;
    const int h    = blockIdx.y, s = blockIdx.z;
    const int wm   = (wid & 3) * 16, wn = (wid >> 2) * 32;
    const uint32_t sb = smem_u32(sm);

    const float* B = in_proj_w + (size_t)(2 * E_SZ + h * 64) * E_SZ;

    float acc[4][4] = {};
    for (int it = 0; it < 3; it++) {
        int k0 = s * 192 + it * 64;
        #pragma unroll
        for (int j = 0; j < 4; j++) {
            int fid = tid + j * 256;
            int row = fid >> 4, c4 = fid & 15;
            const float* a0 = Up + (size_t)(h * 64 + row) * E_SZ + k0 + c4 * 4;
            float4 va = *(const float4*)a0;
            float4 v1 = *(const float4*)(a0 + (size_t)E_SZ * E_SZ);
            float4 bs = *(const float4*)(sample_b + k0 + c4 * 4);
            va.x += v1.x + bs.x; va.y += v1.y + bs.y;
            va.z += v1.z + bs.z; va.w += v1.w + bs.w;
            store_pair(sm, A_H_OFF, A_L_OFF, row, c4, va);
            float4 vb = *(const float4*)(B + (size_t)row * E_SZ + k0 + c4 * 4);
            store_pair(sm, B_H_OFF, B_L_OFF, row, c4, vb);
        }
        __syncthreads();
        mma_tile64_8w(sb, wm, wn, lane, acc);
        __syncthreads();
    }

    float* Pp = P2 + (size_t)(h * 4 + s) * 4096;
    {
        int r0 = wm + (lane >> 2);
        #pragma unroll
        for (int ni = 0; ni < 4; ni++) {
            int c0 = wn + ni * 8 + (lane & 3) * 2;
            *(float2*)(Pp + r0 * 64 + c0) = make_float2(acc[ni][0], acc[ni][1]);
            *(float2*)(Pp + (r0 + 8) * 64 + c0) = make_float2(acc[ni][2], acc[ni][3]);
        }
    }
}

// ---------------------------------------------------------------
// out-proj HMMA partials
// ---------------------------------------------------------------
__global__ __launch_bounds__(256)
void outproj_hmma(const float* __restrict__ P2,
                  const float* __restrict__ in_proj_b,
                  const float* __restrict__ Wo,
                  float* __restrict__ P1)
{
    __shared__ __align__(16) char sm[TILE_SMEM];
    const int tid  = threadIdx.x;
    const int wid  = tid >> 5, lane = tid & 31;
    const int bn   = blockIdx.x * 64, s = blockIdx.z;
    const int wm   = (wid & 3) * 16, wn = (wid >> 2) * 32;
    const uint32_t sb = smem_u32(sm);

    float acc[4][4] = {};
    for (int it = 0; it < 3; it++) {
        int k0 = s * 192 + it * 64;
        int hh = k0 >> 6;
        #pragma unroll
        for (int j = 0; j < 4; j++) {
            int fid = tid + j * 256;
            int row = fid >> 4, c4 = fid & 15;
            const float* pbase = P2 + (size_t)(hh * 4) * 4096 + row * 64 + c4 * 4;
            float4 v = *(const float4*)pbase;
            #pragma unroll
            for (int ss = 1; ss < 4; ss++) {
                float4 p = *(const float4*)(pbase + (size_t)ss * 4096);
                v.x += p.x; v.y += p.y; v.z += p.z; v.w += p.w;
            }
            float4 bv = *(const float4*)(in_proj_b + 2 * E_SZ + k0 + c4 * 4);
            v.x += bv.x; v.y += bv.y; v.z += bv.z; v.w += bv.w;
            store_pair(sm, A_H_OFF, A_L_OFF, row, c4, v);
            float4 vb = *(const float4*)(Wo + (size_t)(bn + row) * E_SZ + k0 + c4 * 4);
            store_pair(sm, B_H_OFF, B_L_OFF, row, c4, vb);
        }
        __syncthreads();
        mma_tile64_8w(sb, wm, wn, lane, acc);
        __syncthreads();
    }

    float* Pp = P1 + (size_t)s * B_SZ * E_SZ;
    {
        int r0 = wm + (lane >> 2);
        #pragma unroll
        for (int ni = 0; ni < 4; ni++) {
            int c0 = bn + wn + ni * 8 + (lane & 3) * 2;
            *(float2*)(Pp + (size_t)r0 * E_SZ + c0) = make_float2(acc[ni][0], acc[ni][1]);
            *(float2*)(Pp + (size_t)(r0 + 8) * E_SZ + c0) = make_float2(acc[ni][2], acc[ni][3]);
        }
    }
}

// ---------------------------------------------------------------
// Fused reduce + broadcast
// ---------------------------------------------------------------
__global__ __launch_bounds__(256)
void bcast_reduce_kernel(const float* __restrict__ P1,
                         const float* __restrict__ bo,
                         const float* __restrict__ conf,
                         float* __restrict__ out)
{
    __shared__ __align__(16) float ao[E_SZ];
    const int b  = blockIdx.x;
    const int n0 = blockIdx.y * 27;
    const int t  = threadIdx.x;
    const float cf = conf[b];

    for (int c = t; c < E_SZ; c += 256) {
        float a0 = P1[(size_t)b * E_SZ + c];
        float a1 = P1[(size_t)(B_SZ + b) * E_SZ + c];
        float a2 = P1[(size_t)(2 * B_SZ + b) * E_SZ + c];
        float a3 = P1[(size_t)(3 * B_SZ + b) * E_SZ + c];
        ao[c] = ((a0 + a1) + (a2 + a3) + bo[c]) * cf;
    }
    __syncthreads();

    const float4* src = (const float4*)ao;
    float4* dstb = (float4*)(out + ((size_t)b * FULLN + n0) * E_SZ);
    const int nrows = min(27, FULLN - n0);
    for (int i = t; i < nrows * 192; i += 256) {
        int r = i / 192, c = i - r * 192;
        dstb[(size_t)r * 192 + c] = src[c];
    }
}

// ---------------------------------------------------------------
extern "C" void kernel_launch(void* const* d_in, const int* in_sizes, int n_in,
                              void* d_out, int out_size)
{
    const float* x           = (const float*)d_in[0];
    const float* bio_embed   = (const float*)d_in[1];
    const float* base_coords = (const float*)d_in[2];
    const float* offsets     = (const float*)d_in[3];
    const float* confidence  = (const float*)d_in[4];
    const float* sample_w    = (const float*)d_in[5];
    const float* sample_b    = (const float*)d_in[6];
    const float* in_proj_w   = (const float*)d_in[7];
    const float* in_proj_b   = (const float*)d_in[8];
    const float* out_proj_w  = (const float*)d_in[9];
    const float* out_proj_b  = (const float*)d_in[10];
    float* out = (float*)d_out;

    float *S, *T, *WS, *P1, *P2, *PB, *WsT, *WkT;
    cudaGetSymbolAddress((void**)&S,   g_S);
    cudaGetSymbolAddress((void**)&T,   g_T);
    cudaGetSymbolAddress((void**)&WS,  g_WS);
    cudaGetSymbolAddress((void**)&P1,  g_P1);
    cudaGetSymbolAddress((void**)&P2,  g_P2);
    cudaGetSymbolAddress((void**)&PB,  g_PB);
    cudaGetSymbolAddress((void**)&WsT, g_WsT);
    cudaGetSymbolAddress((void**)&WkT, g_WkT);

    const int attn_smem = (NB * E_SZ + NHEAD * E_SZ + 2 * NHEAD * NB) * sizeof(float);
    cudaFuncSetAttribute(attn_fuse_kernel,
                         cudaFuncAttributeMaxDynamicSharedMemorySize, attn_smem);

    // 1) qproj partials + both transposes
    k1_front<<<K1_GRID, 256>>>(bio_embed, in_proj_w, sample_w, P1, WsT, WkT);

    // 2) thead + gather half 1 (overlapped)
    k2_thead_gather<<<K2_GRID, 256>>>(P1, in_proj_b, WkT, T,
                                      x, base_coords, offsets, S);

    // 3) QH partials = T @ Ws (K-split 2) + gather half 2 (overlapped)
    k3_gemm1_gather<<<K3_GRID, 256>>>(T, WsT, PB,
                                      x, base_coords, offsets, S);

    // 4) fused scores (sums QH partials) + softmax + weighted-S, one CTA/batch
    attn_fuse_kernel<<<B_SZ, 512, attn_smem>>>(PB, S, WS);

    // 5) U partials = WS @ Ws^T (K-split 2, 128x64 tiles)
    hmma_nt_split<<<dim3(12, 6, 2), 256>>>(WS, sample_w, PB);

    // 6) ctx partials per head (A = Up0+Up1+bs fused)
    ctx_hmma<<<dim3(1, 12, 4), 256>>>(PB, sample_b, in_proj_w, P2);

    // 7) out-proj partials (fused ctx reduce + bv)
    outproj_hmma<<<dim3(12, 1, 4), 256>>>(P2, in_proj_b, out_proj_w, P1);

    // 8) fused reduce + broadcast * confidence
    bcast_reduce_kernel<<<dim3(B_SZ, 19), 256>>>(P1, out_proj_b, confidence, out);
}

// round 14
// speedup vs baseline: 1.0564x; 1.0564x over previous
#include <cuda_runtime.h>
#include <cuda_bf16.h>
#include <math.h>
#include <stdint.h>

#define B_SZ   64
#define FULLN  513
#define E_SZ   768
#define NB     32
#define GRIDSZ 8
#define NHEAD  12
#define HDIM   64
#define NP     (B_SZ * NB)      // 2048

// ---------------- scratch (device globals) ----------------
__device__ float g_S  [NP * E_SZ];
__device__ float g_T  [E_SZ * E_SZ];
__device__ float g_WS [E_SZ * E_SZ];
__device__ float g_P1 [4 * B_SZ * E_SZ];
__device__ float g_P2 [12 * 4 * 64 * 64];
__device__ float g_PB [2 * E_SZ * E_SZ];
__device__ float g_WsT[E_SZ * E_SZ];
__device__ float g_WkT[E_SZ * E_SZ];

// ================= tensor-core helpers =================
__device__ __forceinline__ uint32_t smem_u32(const void* p) {
    uint32_t a;
    asm("{ .reg .u64 t; cvta.to.shared.u64 t, %1; cvt.u32.u64 %0, t; }" : "=r"(a) : "l"(p));
    return a;
}
__device__ __forceinline__ void ldsm4(uint32_t* r, uint32_t addr) {
    asm volatile("ldmatrix.sync.aligned.m8n8.x4.shared.b16 {%0,%1,%2,%3}, [%4];"
        : "=r"(r[0]), "=r"(r[1]), "=r"(r[2]), "=r"(r[3]) : "r"(addr));
}
__device__ __forceinline__ void mma16816(float* d, const uint32_t* a, const uint32_t* b) {
    asm volatile("mma.sync.aligned.m16n8k16.row.col.f32.bf16.bf16.f32 "
        "{%0,%1,%2,%3}, {%4,%5,%6,%7}, {%8,%9}, {%0,%1,%2,%3};"
        : "+f"(d[0]), "+f"(d[1]), "+f"(d[2]), "+f"(d[3])
        : "r"(a[0]), "r"(a[1]), "r"(a[2]), "r"(a[3]), "r"(b[0]), "r"(b[1]));
}
__device__ __forceinline__ void cvt_hl(float4 v, uint2& hi, uint2& lo) {
    __nv_bfloat16 h0 = __float2bfloat16(v.x), h1 = __float2bfloat16(v.y);
    __nv_bfloat16 h2 = __float2bfloat16(v.z), h3 = __float2bfloat16(v.w);
    __nv_bfloat16 l0 = __float2bfloat16(v.x - __bfloat162float(h0));
    __nv_bfloat16 l1 = __float2bfloat16(v.y - __bfloat162float(h1));
    __nv_bfloat16 l2 = __float2bfloat16(v.z - __bfloat162float(h2));
    __nv_bfloat16 l3 = __float2bfloat16(v.w - __bfloat162float(h3));
    __nv_bfloat162 hp0 = __halves2bfloat162(h0, h1), hp1 = __halves2bfloat162(h2, h3);
    __nv_bfloat162 lp0 = __halves2bfloat162(l0, l1), lp1 = __halves2bfloat162(l2, l3);
    hi = make_uint2(*(uint32_t*)&hp0, *(uint32_t*)&hp1);
    lo = make_uint2(*(uint32_t*)&lp0, *(uint32_t*)&lp1);
}

#define PITCH   144
#define A_H_OFF 0
#define A_L_OFF 9216
#define B_H_OFF 18432
#define B_L_OFF 27648
#define TILE_SMEM 36864

__device__ __forceinline__ void store_pair(char* sm, int base_h, int base_l,
                                           int row, int c4, float4 v) {
    uint2 hi, lo;
    cvt_hl(v, hi, lo);
    *(uint2*)(sm + base_h + row * PITCH + c4 * 8) = hi;
    *(uint2*)(sm + base_l + row * PITCH + c4 * 8) = lo;
}

// 64-K tile compute, 8 warps: warp tile 16x32.
__device__ __forceinline__ void mma_tile64_8w(uint32_t sb, int wm, int wn, int lane,
                                              float acc[4][4]) {
    #pragma unroll
    for (int ks = 0; ks < 4; ks++) {
        uint32_t a_h[4], a_l[4], b_h[4][2], b_l[4][2];
        {
            uint32_t r  = wm + (lane & 15);
            uint32_t cb = ks * 32 + ((lane >> 4) << 4);
            ldsm4(a_h, sb + A_H_OFF + r * PITCH + cb);
            ldsm4(a_l, sb + A_L_OFF + r * PITCH + cb);
        }
        #pragma unroll
        for (int g = 0; g < 2; g++) {
            uint32_t n  = wn + g * 16 + (lane & 7) + (((lane >> 4) & 1) << 3);
            uint32_t cb = ks * 32 + (((lane >> 3) & 1) << 4);
            uint32_t t[4];
            ldsm4(t, sb + B_H_OFF + n * PITCH + cb);
            b_h[g*2][0] = t[0]; b_h[g*2][1] = t[1];
            b_h[g*2+1][0] = t[2]; b_h[g*2+1][1] = t[3];
            ldsm4(t, sb + B_L_OFF + n * PITCH + cb);
            b_l[g*2][0] = t[0]; b_l[g*2][1] = t[1];
            b_l[g*2+1][0] = t[2]; b_l[g*2+1][1] = t[3];
        }
        #pragma unroll
        for (int ni = 0; ni < 4; ni++) {
            mma16816(acc[ni], a_h, b_h[ni]);
            mma16816(acc[ni], a_h, b_l[ni]);
            mma16816(acc[ni], a_l, b_h[ni]);
        }
    }
}

// generic NT tile GEMM core (64x64 CTA tile)
__device__ __forceinline__ void hmma_tile_core(
    char* sm, uint32_t sb, int tid,
    const float* __restrict__ A, const float* __restrict__ B,
    const float* __restrict__ bias, float* __restrict__ Cp,
    int bm, int bn, int kbase, int niter)
{
    const int wid = tid >> 5, lane = tid & 31;
    const int wm = (wid & 3) * 16, wn = (wid >> 2) * 32;

    float acc[4][4] = {};
    float4 pa[4], pb[4];
    #pragma unroll
    for (int j = 0; j < 4; j++) {
        int fid = tid + j * 256;
        int row = fid >> 4, c4 = fid & 15;
        pa[j] = *(const float4*)(A + (size_t)(bm + row) * E_SZ + kbase + c4 * 4);
        pb[j] = *(const float4*)(B + (size_t)(bn + row) * E_SZ + kbase + c4 * 4);
    }
    for (int it = 0; it < niter; it++) {
        #pragma unroll
        for (int j = 0; j < 4; j++) {
            int fid = tid + j * 256;
            int row = fid >> 4, c4 = fid & 15;
            store_pair(sm, A_H_OFF, A_L_OFF, row, c4, pa[j]);
            store_pair(sm, B_H_OFF, B_L_OFF, row, c4, pb[j]);
        }
        __syncthreads();
        if (it + 1 < niter) {
            int k0 = kbase + (it + 1) * 64;
            #pragma unroll
            for (int j = 0; j < 4; j++) {
                int fid = tid + j * 256;
                int row = fid >> 4, c4 = fid & 15;
                pa[j] = *(const float4*)(A + (size_t)(bm + row) * E_SZ + k0 + c4 * 4);
                pb[j] = *(const float4*)(B + (size_t)(bn + row) * E_SZ + k0 + c4 * 4);
            }
        }
        mma_tile64_8w(sb, wm, wn, lane, acc);
        __syncthreads();
    }
    {
        int r0 = bm + wm + (lane >> 2);
        #pragma unroll
        for (int ni = 0; ni < 4; ni++) {
            int c0 = bn + wn + ni * 8 + (lane & 3) * 2;
            float bb0 = bias ? bias[c0] : 0.f;
            float bb1 = bias ? bias[c0 + 1] : 0.f;
            *(float2*)(Cp + (size_t)r0 * E_SZ + c0) =
                make_float2(acc[ni][0] + bb0, acc[ni][1] + bb1);
            *(float2*)(Cp + (size_t)(r0 + 8) * E_SZ + c0) =
                make_float2(acc[ni][2] + bb0, acc[ni][3] + bb1);
        }
    }
}

// ---------------------------------------------------------------
// gather one (b,p) point; 192 active lanes of a 256-thread block
// ---------------------------------------------------------------
__device__ __forceinline__ void gather_point(
    int bp, int t,
    const float* __restrict__ x,
    const float* __restrict__ bc,
    const float* __restrict__ off,
    float* __restrict__ S)
{
    if (t >= 192) return;
    const int b = bp >> 5, p = bp & 31;

    float cx = fminf(fmaxf(bc[p*3+0] + off[bp*3+0], -1.f), 1.f);
    float cy = fminf(fmaxf(bc[p*3+1] + off[bp*3+1], -1.f), 1.f);
    float cz = fminf(fmaxf(bc[p*3+2] + off[bp*3+2], -1.f), 1.f);

    float ix = (cx + 1.0f) * 0.5f * (GRIDSZ - 1);
    float iy = (cy + 1.0f) * 0.5f * (GRIDSZ - 1);
    float iz = (cz + 1.0f) * 0.5f * (GRIDSZ - 1);

    float fx = floorf(ix), fy = floorf(iy), fz = floorf(iz);
    float wx = ix - fx, wy = iy - fy, wz = iz - fz;

    int x0 = min(max((int)fx, 0), GRIDSZ-1);
    int y0 = min(max((int)fy, 0), GRIDSZ-1);
    int z0 = min(max((int)fz, 0), GRIDSZ-1);
    int x1 = min(x0 + 1, GRIDSZ-1);
    int y1 = min(y0 + 1, GRIDSZ-1);
    int z1 = min(z0 + 1, GRIDSZ-1);

    const float* xb = x + ((size_t)b * FULLN + 1) * E_SZ;

    int idx[8];
    idx[0] = (((z0*GRIDSZ)+y0)*GRIDSZ + x0) * E_SZ;
    idx[1] = (((z0*GRIDSZ)+y0)*GRIDSZ + x1) * E_SZ;
    idx[2] = (((z0*GRIDSZ)+y1)*GRIDSZ + x0) * E_SZ;
    idx[3] = (((z0*GRIDSZ)+y1)*GRIDSZ + x1) * E_SZ;
    idx[4] = (((z1*GRIDSZ)+y0)*GRIDSZ + x0) * E_SZ;
    idx[5] = (((z1*GRIDSZ)+y0)*GRIDSZ + x1) * E_SZ;
    idx[6] = (((z1*GRIDSZ)+y1)*GRIDSZ + x0) * E_SZ;
    idx[7] = (((z1*GRIDSZ)+y1)*GRIDSZ + x1) * E_SZ;

    float w[8];
    w[0] = (1-wz)*(1-wy)*(1-wx);
    w[1] = (1-wz)*(1-wy)*wx;
    w[2] = (1-wz)*wy*(1-wx);
    w[3] = (1-wz)*wy*wx;
    w[4] = wz*(1-wy)*(1-wx);
    w[5] = wz*(1-wy)*wx;
    w[6] = wz*wy*(1-wx);
    w[7] = wz*wy*wx;

    float4* outv = (float4*)(S + (size_t)bp * E_SZ);
    float4 acc = make_float4(0.f,0.f,0.f,0.f);
    #pragma unroll
    for (int i = 0; i < 8; i++) {
        float4 v = ((const float4*)(xb + idx[i]))[t];
        acc.x = fmaf(w[i], v.x, acc.x);
        acc.y = fmaf(w[i], v.y, acc.y);
        acc.z = fmaf(w[i], v.z, acc.z);
        acc.w = fmaf(w[i], v.w, acc.w);
    }
    outv[t] = acc;
}

// ---------------------------------------------------------------
// k1: qproj (48) | transposes (1152)
// ---------------------------------------------------------------
#define K1_QPROJ 48
#define K1_GRID  (K1_QPROJ + 1152)

__global__ __launch_bounds__(256)
void k1_front(const float* __restrict__ bio,
              const float* __restrict__ in_proj_w,
              const float* __restrict__ sample_w,
              float* __restrict__ P1,
              float* __restrict__ WsT,
              float* __restrict__ WkT)
{
    __shared__ __align__(16) char sm[TILE_SMEM];
    const int bid = blockIdx.x;
    const int t   = threadIdx.x;

    if (bid < K1_QPROJ) {
        const int n = bid % 12, z = bid / 12;
        hmma_tile_core(sm, smem_u32(sm), t, bio, in_proj_w, nullptr,
                       P1 + (size_t)z * B_SZ * E_SZ, 0, n * 64, z * 192, 3);
    } else {
        int tb = bid - K1_QPROJ;
        const int zsel = tb / 576; tb -= zsel * 576;
        const int bx = (tb % 24) * 32, by = (tb / 24) * 32;
        const float* A = zsel ? (in_proj_w + (size_t)E_SZ * E_SZ) : sample_w;
        float* At      = zsel ? WkT : WsT;
        float (*ts)[33] = (float(*)[33])sm;
        const int tx = t & 31, ty = t >> 5;
        #pragma unroll
        for (int i = 0; i < 32; i += 8)
            ts[ty + i][tx] = A[(size_t)(by + ty + i) * E_SZ + bx + tx];
        __syncthreads();
        #pragma unroll
        for (int i = 0; i < 32; i += 8)
            At[(size_t)(bx + ty + i) * E_SZ + by + tx] = ts[tx][ty + i];
    }
}

// ---------------------------------------------------------------
// k2: thead (144) | gather half 1 (1024)
// ---------------------------------------------------------------
#define K2_THEAD 144
#define K2_GRID  (K2_THEAD + 1024)

__global__ __launch_bounds__(256)
void k2_thead_gather(const float* __restrict__ P1,
                     const float* __restrict__ in_proj_b,
                     const float* __restrict__ WkT,
                     float* __restrict__ T,
                     const float* __restrict__ x,
                     const float* __restrict__ bc,
                     const float* __restrict__ off,
                     float* __restrict__ S)
{
    __shared__ __align__(16) char sm[TILE_SMEM];
    const int bid = blockIdx.x;
    const int tid = threadIdx.x;

    if (bid >= K2_THEAD) {
        gather_point(bid - K2_THEAD, tid, x, bc, off, S);
        return;
    }

    const int wid  = tid >> 5, lane = tid & 31;
    const int e0   = (bid % 12) * 64;
    const int h    = bid / 12;
    const int wm   = (wid & 3) * 16, wn = (wid >> 2) * 32;
    const uint32_t sb = smem_u32(sm);

    #pragma unroll
    for (int j = 0; j < 4; j++) {
        int fid = tid + j * 256;
        int row = fid >> 4, c4 = fid & 15;
        const float* pbase = P1 + (size_t)row * E_SZ + h * 64 + c4 * 4;
        float4 v = *(const float4*)pbase;
        #pragma unroll
        for (int s = 1; s < 4; s++) {
            float4 p = *(const float4*)(pbase + (size_t)s * B_SZ * E_SZ);
            v.x += p.x; v.y += p.y; v.z += p.z; v.w += p.w;
        }
        float4 bq = *(const float4*)(in_proj_b + h * 64 + c4 * 4);
        v.x += bq.x; v.y += bq.y; v.z += bq.z; v.w += bq.w;
        store_pair(sm, A_H_OFF, A_L_OFF, row, c4, v);
        float4 vb = *(const float4*)(WkT + (size_t)(e0 + row) * E_SZ + h * 64 + c4 * 4);
        store_pair(sm, B_H_OFF, B_L_OFF, row, c4, vb);
    }
    __syncthreads();

    float acc[4][4] = {};
    mma_tile64_8w(sb, wm, wn, lane, acc);

    {
        int r0 = h * 64 + wm + (lane >> 2);
        #pragma unroll
        for (int ni = 0; ni < 4; ni++) {
            int c0 = e0 + wn + ni * 8 + (lane & 3) * 2;
            *(float2*)(T + (size_t)r0 * E_SZ + c0) = make_float2(acc[ni][0], acc[ni][1]);
            *(float2*)(T + (size_t)(r0 + 8) * E_SZ + c0) = make_float2(acc[ni][2], acc[ni][3]);
        }
    }
}

// ---------------------------------------------------------------
// Big NT GEMM body, CTA tile 128x64 (8 warps, warp tile 32x32)
// ---------------------------------------------------------------
#define BG_A_H 0
#define BG_A_L 18432
#define BG_B_H 36864
#define BG_B_L 46080
#define BG_SMEM 55296

__device__ __forceinline__ void big_nt_body(
    char* sm, int tid,
    const float* __restrict__ A, const float* __restrict__ B,
    float* __restrict__ PB, int bm, int bn, int z)
{
    const int wid = tid >> 5, lane = tid & 31;
    const int wm = (wid & 3) * 32, wn = (wid >> 2) * 32;
    const int kbase = z * 384;
    const uint32_t sb = smem_u32(sm);

    float acc[2][4][4] = {};
    float4 pa[8], pb[4];

    #pragma unroll
    for (int j = 0; j < 8; j++) {
        int fid = tid + j * 256;
        int row = fid >> 4, c4 = fid & 15;
        pa[j] = *(const float4*)(A + (size_t)(bm + row) * E_SZ + kbase + c4 * 4);
    }
    #pragma unroll
    for (int j = 0; j < 4; j++) {
        int fid = tid + j * 256;
        int row = fid >> 4, c4 = fid & 15;
        pb[j] = *(const float4*)(B + (size_t)(bn + row) * E_SZ + kbase + c4 * 4);
    }

    for (int it = 0; it < 6; it++) {
        #pragma unroll
        for (int j = 0; j < 8; j++) {
            int fid = tid + j * 256;
            int row = fid >> 4, c4 = fid & 15;
            store_pair(sm, BG_A_H, BG_A_L, row, c4, pa[j]);
        }
        #pragma unroll
        for (int j = 0; j < 4; j++) {
            int fid = tid + j * 256;
            int row = fid >> 4, c4 = fid & 15;
            store_pair(sm, BG_B_H, BG_B_L, row, c4, pb[j]);
        }
        __syncthreads();
        if (it + 1 < 6) {
            int k0 = kbase + (it + 1) * 64;
            #pragma unroll
            for (int j = 0; j < 8; j++) {
                int fid = tid + j * 256;
                int row = fid >> 4, c4 = fid & 15;
                pa[j] = *(const float4*)(A + (size_t)(bm + row) * E_SZ + k0 + c4 * 4);
            }
            #pragma unroll
            for (int j = 0; j < 4; j++) {
                int fid = tid + j * 256;
                int row = fid >> 4, c4 = fid & 15;
                pb[j] = *(const float4*)(B + (size_t)(bn + row) * E_SZ + k0 + c4 * 4);
            }
        }
        #pragma unroll
        for (int ks = 0; ks < 4; ks++) {
            uint32_t a_h[2][4], a_l[2][4], b_h[4][2], b_l[4][2];
            #pragma unroll
            for (int mi = 0; mi < 2; mi++) {
                uint32_t r  = wm + mi * 16 + (lane & 15);
                uint32_t cb = ks * 32 + ((lane >> 4) << 4);
                ldsm4(a_h[mi], sb + BG_A_H + r * PITCH + cb);
                ldsm4(a_l[mi], sb + BG_A_L + r * PITCH + cb);
            }
            #pragma unroll
            for (int g = 0; g < 2; g++) {
                uint32_t n  = wn + g * 16 + (lane & 7) + (((lane >> 4) & 1) << 3);
                uint32_t cb = ks * 32 + (((lane >> 3) & 1) << 4);
                uint32_t t[4];
                ldsm4(t, sb + BG_B_H + n * PITCH + cb);
                b_h[g*2][0] = t[0]; b_h[g*2][1] = t[1];
                b_h[g*2+1][0] = t[2]; b_h[g*2+1][1] = t[3];
                ldsm4(t, sb + BG_B_L + n * PITCH + cb);
                b_l[g*2][0] = t[0]; b_l[g*2][1] = t[1];
                b_l[g*2+1][0] = t[2]; b_l[g*2+1][1] = t[3];
            }
            #pragma unroll
            for (int mi = 0; mi < 2; mi++)
                #pragma unroll
                for (int ni = 0; ni < 4; ni++) {
                    mma16816(acc[mi][ni], a_h[mi], b_h[ni]);
                    mma16816(acc[mi][ni], a_h[mi], b_l[ni]);
                    mma16816(acc[mi][ni], a_l[mi], b_h[ni]);
                }
        }
        __syncthreads();
    }

    float* Cp = PB + (size_t)z * E_SZ * E_SZ;
    #pragma unroll
    for (int mi = 0; mi < 2; mi++) {
        int r0 = bm + wm + mi * 16 + (lane >> 2);
        #pragma unroll
        for (int ni = 0; ni < 4; ni++) {
            int c0 = bn + wn + ni * 8 + (lane & 3) * 2;
            *(float2*)(Cp + (size_t)r0 * E_SZ + c0) =
                make_float2(acc[mi][ni][0], acc[mi][ni][1]);
            *(float2*)(Cp + (size_t)(r0 + 8) * E_SZ + c0) =
                make_float2(acc[mi][ni][2], acc[mi][ni][3]);
        }
    }
}

// ---------------------------------------------------------------
// k3: gemm1 (144 flattened) | gather half 2 (1024)
// ---------------------------------------------------------------
#define K3_GEMM 144
#define K3_GRID (K3_GEMM + 1024)

__global__ __launch_bounds__(256)
void k3_gemm1_gather(const float* __restrict__ T,
                     const float* __restrict__ WsT,
                     float* __restrict__ PB,
                     const float* __restrict__ x,
                     const float* __restrict__ bc,
                     const float* __restrict__ off,
                     float* __restrict__ S)
{
    __shared__ __align__(16) char sm[BG_SMEM];
    const int bid = blockIdx.x;
    const int tid = threadIdx.x;

    if (bid >= K3_GEMM) {
        gather_point(1024 + (bid - K3_GEMM), tid, x, bc, off, S);
        return;
    }
    const int n = bid % 12;
    const int rest = bid / 12;
    const int m = rest % 6, z = rest / 6;
    big_nt_body(sm, tid, T, WsT, PB, m * 128, n * 64, z);
}

// gemm2: plain big NT (grid (12,6,2))
__global__ __launch_bounds__(256)
void hmma_nt_split(const float* __restrict__ A,
                   const float* __restrict__ B,
                   float* __restrict__ PB)
{
    __shared__ __align__(16) char sm[BG_SMEM];
    big_nt_body(sm, threadIdx.x, A, B, PB,
                blockIdx.y * 128, blockIdx.x * 64, blockIdx.z);
}

// ---------------------------------------------------------------
// Fused attention (HGRP=4, all 16 warps active):
// grid (64 b, 3 head-groups of 4), 512 thr.
// smem: S (32x768) + q (4x768) + sc/at (2x4x32)
// ---------------------------------------------------------------
#define HGRP 4
__global__ __launch_bounds__(512)
void attn_fuse_kernel(const float* __restrict__ QHp,
                      const float* __restrict__ S,
                      float* __restrict__ WS)
{
    extern __shared__ float smf[];
    float* Ssm = smf;                        // 32*768
    float* qsm = smf + NB * E_SZ;            // 4*768
    float* sc  = qsm + HGRP * E_SZ;          // 4*32
    float* at  = sc + HGRP * NB;             // 4*32

    const int b  = blockIdx.x;
    const int h0 = blockIdx.y * HGRP;
    const int t  = threadIdx.x;
    const int w = t >> 5, lane = t & 31;

    // stage 0: S tile + q rows (partials summed)
    {
        const float4* src = (const float4*)(S + (size_t)b * NB * E_SZ);
        float4* dst = (float4*)Ssm;
        #pragma unroll
        for (int i = t; i < NB * E_SZ / 4; i += 512) dst[i] = src[i];
        float4* qdst = (float4*)qsm;
        for (int i = t; i < HGRP * E_SZ / 4; i += 512) {
            int hl = i / 192, c4 = i - hl * 192;
            const float4* q0 = (const float4*)(QHp + (size_t)((h0 + hl) * 64 + b) * E_SZ) + c4;
            float4 v0 = *q0;
            float4 v1 = *(const float4*)((const float*)q0 + (size_t)E_SZ * E_SZ);
            v0.x += v1.x; v0.y += v1.y; v0.z += v1.z; v0.w += v1.w;
            qdst[i] = v0;
        }
    }
    __syncthreads();

    // stage 2: scores. 16 warps = 2 head-pairs x 8 p-groups(4).
    {
        const int hp = w >> 3, pg = w & 7;
        const int ha = hp * 2, hb = ha + 1;
        float qa[24], qb[24];
        #pragma unroll
        for (int i = 0; i < 24; i++) {
            qa[i] = qsm[ha * E_SZ + lane + i * 32];
            qb[i] = qsm[hb * E_SZ + lane + i * 32];
        }
        #pragma unroll
        for (int p = 0; p < 4; p++) {
            const int pp = pg * 4 + p;
            const float* sr = Ssm + pp * E_SZ;
            float acca = 0.f, accb = 0.f;
            #pragma unroll
            for (int i = 0; i < 24; i++) {
                float sv = sr[lane + i * 32];
                acca = fmaf(qa[i], sv, acca);
                accb = fmaf(qb[i], sv, accb);
            }
            #pragma unroll
            for (int o = 16; o; o >>= 1) {
                acca += __shfl_xor_sync(0xffffffffu, acca, o);
                accb += __shfl_xor_sync(0xffffffffu, accb, o);
            }
            if (lane == 0) {
                sc[ha * 32 + pp] = acca * 0.125f;
                sc[hb * 32 + pp] = accb * 0.125f;
            }
        }
    }
    __syncthreads();

    // stage 3: softmax per head (4 warps)
    if (w < HGRP) {
        float s = sc[w*32 + lane];
        float m = s;
        #pragma unroll
        for (int o = 16; o; o >>= 1) m = fmaxf(m, __shfl_xor_sync(0xffffffffu, m, o));
        float e = __expf(s - m);
        float sum = e;
        #pragma unroll
        for (int o = 16; o; o >>= 1) sum += __shfl_xor_sync(0xffffffffu, sum, o);
        at[w*32 + lane] = e / sum;
    }
    __syncthreads();

    // stage 4: weighted S. 16 warps = 2 head-pairs x 8 c-groups(96).
    {
        const int hp = w >> 3, cg = w & 7;
        const int ha = hp * 2, hb = ha + 1;
        float ata[32], atb[32];
        #pragma unroll
        for (int p = 0; p < 32; p++) {
            ata[p] = at[ha * 32 + p];
            atb[p] = at[hb * 32 + p];
        }
        float* wrow_a = WS + (size_t)((h0 + ha) * 64 + b) * E_SZ;
        float* wrow_b = WS + (size_t)((h0 + hb) * 64 + b) * E_SZ;
        #pragma unroll
        for (int j = 0; j < 3; j++) {
            const int c = cg * 96 + j * 32 + lane;
            float acca = 0.f, accb = 0.f;
            #pragma unroll
            for (int p = 0; p < 32; p++) {
                float sv = Ssm[p * E_SZ + c];
                acca = fmaf(ata[p], sv, acca);
                accb = fmaf(atb[p], sv, accb);
            }
            wrow_a[c] = acca;
            wrow_b[c] = accb;
        }
    }
}

// ---------------------------------------------------------------
// ctx HMMA: A = Up0 + Up1 + bs (fused), B = Wv_h. grid (1,12,4)
// ---------------------------------------------------------------
__global__ __launch_bounds__(256)
void ctx_hmma(const float* __restrict__ Up,
              const float* __restrict__ sample_b,
              const float* __restrict__ in_proj_w,
              float* __restrict__ P2)
{
    __shared__ __align__(16) char sm[TILE_SMEM];
    const int tid  = threadIdx.x;
    const int wid  = tid >> 5, lane = tid & 31;
    const int h    = blockIdx.y, s = blockIdx.z;
    const int wm   = (wid & 3) * 16, wn = (wid >> 2) * 32;
    const uint32_t sb = smem_u32(sm);

    const float* B = in_proj_w + (size_t)(2 * E_SZ + h * 64) * E_SZ;

    float acc[4][4] = {};
    for (int it = 0; it < 3; it++) {
        int k0 = s * 192 + it * 64;
        #pragma unroll
        for (int j = 0; j < 4; j++) {
            int fid = tid + j * 256;
            int row = fid >> 4, c4 = fid & 15;
            const float* a0 = Up + (size_t)(h * 64 + row) * E_SZ + k0 + c4 * 4;
            float4 va = *(const float4*)a0;
            float4 v1 = *(const float4*)(a0 + (size_t)E_SZ * E_SZ);
            float4 bs = *(const float4*)(sample_b + k0 + c4 * 4);
            va.x += v1.x + bs.x; va.y += v1.y + bs.y;
            va.z += v1.z + bs.z; va.w += v1.w + bs.w;
            store_pair(sm, A_H_OFF, A_L_OFF, row, c4, va);
            float4 vb = *(const float4*)(B + (size_t)row * E_SZ + k0 + c4 * 4);
            store_pair(sm, B_H_OFF, B_L_OFF, row, c4, vb);
        }
        __syncthreads();
        mma_tile64_8w(sb, wm, wn, lane, acc);
        __syncthreads();
    }

    float* Pp = P2 + (size_t)(h * 4 + s) * 4096;
    {
        int r0 = wm + (lane >> 2);
        #pragma unroll
        for (int ni = 0; ni < 4; ni++) {
            int c0 = wn + ni * 8 + (lane & 3) * 2;
            *(float2*)(Pp + r0 * 64 + c0) = make_float2(acc[ni][0], acc[ni][1]);
            *(float2*)(Pp + (r0 + 8) * 64 + c0) = make_float2(acc[ni][2], acc[ni][3]);
        }
    }
}

// ---------------------------------------------------------------
// out-proj HMMA partials
// ---------------------------------------------------------------
__global__ __launch_bounds__(256)
void outproj_hmma(const float* __restrict__ P2,
                  const float* __restrict__ in_proj_b,
                  const float* __restrict__ Wo,
                  float* __restrict__ P1)
{
    __shared__ __align__(16) char sm[TILE_SMEM];
    const int tid  = threadIdx.x;
    const int wid  = tid >> 5, lane = tid & 31;
    const int bn   = blockIdx.x * 64, s = blockIdx.z;
    const int wm   = (wid & 3) * 16, wn = (wid >> 2) * 32;
    const uint32_t sb = smem_u32(sm);

    float acc[4][4] = {};
    for (int it = 0; it < 3; it++) {
        int k0 = s * 192 + it * 64;
        int hh = k0 >> 6;
        #pragma unroll
        for (int j = 0; j < 4; j++) {
            int fid = tid + j * 256;
            int row = fid >> 4, c4 = fid & 15;
            const float* pbase = P2 + (size_t)(hh * 4) * 4096 + row * 64 + c4 * 4;
            float4 v = *(const float4*)pbase;
            #pragma unroll
            for (int ss = 1; ss < 4; ss++) {
                float4 p = *(const float4*)(pbase + (size_t)ss * 4096);
                v.x += p.x; v.y += p.y; v.z += p.z; v.w += p.w;
            }
            float4 bv = *(const float4*)(in_proj_b + 2 * E_SZ + k0 + c4 * 4);
            v.x += bv.x; v.y += bv.y; v.z += bv.z; v.w += bv.w;
            store_pair(sm, A_H_OFF, A_L_OFF, row, c4, v);
            float4 vb = *(const float4*)(Wo + (size_t)(bn + row) * E_SZ + k0 + c4 * 4);
            store_pair(sm, B_H_OFF, B_L_OFF, row, c4, vb);
        }
        __syncthreads();
        mma_tile64_8w(sb, wm, wn, lane, acc);
        __syncthreads();
    }

    float* Pp = P1 + (size_t)s * B_SZ * E_SZ;
    {
        int r0 = wm + (lane >> 2);
        #pragma unroll
        for (int ni = 0; ni < 4; ni++) {
            int c0 = bn + wn + ni * 8 + (lane & 3) * 2;
            *(float2*)(Pp + (size_t)r0 * E_SZ + c0) = make_float2(acc[ni][0], acc[ni][1]);
            *(float2*)(Pp + (size_t)(r0 + 8) * E_SZ + c0) = make_float2(acc[ni][2], acc[ni][3]);
        }
    }
}

// ---------------------------------------------------------------
// Fused reduce + broadcast
// ---------------------------------------------------------------
__global__ __launch_bounds__(256)
void bcast_reduce_kernel(const float* __restrict__ P1,
                         const float* __restrict__ bo,
                         const float* __restrict__ conf,
                         float* __restrict__ out)
{
    __shared__ __align__(16) float ao[E_SZ];
    const int b  = blockIdx.x;
    const int n0 = blockIdx.y * 27;
    const int t  = threadIdx.x;
    const float cf = conf[b];

    for (int c = t; c < E_SZ; c += 256) {
        float a0 = P1[(size_t)b * E_SZ + c];
        float a1 = P1[(size_t)(B_SZ + b) * E_SZ + c];
        float a2 = P1[(size_t)(2 * B_SZ + b) * E_SZ + c];
        float a3 = P1[(size_t)(3 * B_SZ + b) * E_SZ + c];
        ao[c] = ((a0 + a1) + (a2 + a3) + bo[c]) * cf;
    }
    __syncthreads();

    const float4* src = (const float4*)ao;
    float4* dstb = (float4*)(out + ((size_t)b * FULLN + n0) * E_SZ);
    const int nrows = min(27, FULLN - n0);
    for (int i = t; i < nrows * 192; i += 256) {
        int r = i / 192, c = i - r * 192;
        dstb[(size_t)r * 192 + c] = src[c];
    }
}

// ---------------------------------------------------------------
extern "C" void kernel_launch(void* const* d_in, const int* in_sizes, int n_in,
                              void* d_out, int out_size)
{
    const float* x           = (const float*)d_in[0];
    const float* bio_embed   = (const float*)d_in[1];
    const float* base_coords = (const float*)d_in[2];
    const float* offsets     = (const float*)d_in[3];
    const float* confidence  = (const float*)d_in[4];
    const float* sample_w    = (const float*)d_in[5];
    const float* sample_b    = (const float*)d_in[6];
    const float* in_proj_w   = (const float*)d_in[7];
    const float* in_proj_b   = (const float*)d_in[8];
    const float* out_proj_w  = (const float*)d_in[9];
    const float* out_proj_b  = (const float*)d_in[10];
    float* out = (float*)d_out;

    float *S, *T, *WS, *P1, *P2, *PB, *WsT, *WkT;
    cudaGetSymbolAddress((void**)&S,   g_S);
    cudaGetSymbolAddress((void**)&T,   g_T);
    cudaGetSymbolAddress((void**)&WS,  g_WS);
    cudaGetSymbolAddress((void**)&P1,  g_P1);
    cudaGetSymbolAddress((void**)&P2,  g_P2);
    cudaGetSymbolAddress((void**)&PB,  g_PB);
    cudaGetSymbolAddress((void**)&WsT, g_WsT);
    cudaGetSymbolAddress((void**)&WkT, g_WkT);

    const int attn_smem = (NB * E_SZ + HGRP * E_SZ + 2 * HGRP * NB) * sizeof(float);
    cudaFuncSetAttribute(attn_fuse_kernel,
                         cudaFuncAttributeMaxDynamicSharedMemorySize, attn_smem);

    // 1) qproj partials + both transposes
    k1_front<<<K1_GRID, 256>>>(bio_embed, in_proj_w, sample_w, P1, WsT, WkT);

    // 2) thead + gather half 1 (overlapped)
    k2_thead_gather<<<K2_GRID, 256>>>(P1, in_proj_b, WkT, T,
                                      x, base_coords, offsets, S);

    // 3) QH partials = T @ Ws (K-split 2) + gather half 2 (overlapped)
    k3_gemm1_gather<<<K3_GRID, 256>>>(T, WsT, PB,
                                      x, base_coords, offsets, S);

    // 4) fused scores + softmax + weighted-S (192 CTAs, 16 warps active)
    attn_fuse_kernel<<<dim3(B_SZ, 3), 512, attn_smem>>>(PB, S, WS);

    // 5) U partials = WS @ Ws^T (K-split 2, 128x64 tiles)
    hmma_nt_split<<<dim3(12, 6, 2), 256>>>(WS, sample_w, PB);

    // 6) ctx partials per head (A = Up0+Up1+bs fused)
    ctx_hmma<<<dim3(1, 12, 4), 256>>>(PB, sample_b, in_proj_w, P2);

    // 7) out-proj partials (fused ctx reduce + bv)
    outproj_hmma<<<dim3(12, 1, 4), 256>>>(P2, in_proj_b, out_proj_w, P1);

    // 8) fused reduce + broadcast * confidence
    bcast_reduce_kernel<<<dim3(B_SZ, 19), 256>>>(P1, out_proj_b, confidence, out);
}

// round 15
// speedup vs baseline: 1.0640x; 1.0072x over previous
#include <cuda_runtime.h>
#include <cuda_bf16.h>
#include <math.h>
#include <stdint.h>

#define B_SZ   64
#define FULLN  513
#define E_SZ   768
#define NB     32
#define GRIDSZ 8
#define NHEAD  12
#define HDIM   64
#define NP     (B_SZ * NB)      // 2048

// ---------------- scratch (device globals) ----------------
__device__ float g_S  [NP * E_SZ];
__device__ float g_T  [E_SZ * E_SZ];
__device__ float g_WS [E_SZ * E_SZ];
__device__ float g_P1 [4 * B_SZ * E_SZ];
__device__ float g_P2 [12 * 4 * 64 * 64];
__device__ float g_PB [2 * E_SZ * E_SZ];      // QH partials
__device__ float g_WV [2 * E_SZ * E_SZ];      // M = Wv@Ws partials
__device__ float g_B2 [E_SZ];                 // bias2 = Wv@bs
__device__ float g_WsT[E_SZ * E_SZ];
__device__ float g_WkT[E_SZ * E_SZ];

// ================= tensor-core helpers =================
__device__ __forceinline__ uint32_t smem_u32(const void* p) {
    uint32_t a;
    asm("{ .reg .u64 t; cvta.to.shared.u64 t, %1; cvt.u32.u64 %0, t; }" : "=r"(a) : "l"(p));
    return a;
}
__device__ __forceinline__ void ldsm4(uint32_t* r, uint32_t addr) {
    asm volatile("ldmatrix.sync.aligned.m8n8.x4.shared.b16 {%0,%1,%2,%3}, [%4];"
        : "=r"(r[0]), "=r"(r[1]), "=r"(r[2]), "=r"(r[3]) : "r"(addr));
}
__device__ __forceinline__ void mma16816(float* d, const uint32_t* a, const uint32_t* b) {
    asm volatile("mma.sync.aligned.m16n8k16.row.col.f32.bf16.bf16.f32 "
        "{%0,%1,%2,%3}, {%4,%5,%6,%7}, {%8,%9}, {%0,%1,%2,%3};"
        : "+f"(d[0]), "+f"(d[1]), "+f"(d[2]), "+f"(d[3])
        : "r"(a[0]), "r"(a[1]), "r"(a[2]), "r"(a[3]), "r"(b[0]), "r"(b[1]));
}
__device__ __forceinline__ void cvt_hl(float4 v, uint2& hi, uint2& lo) {
    __nv_bfloat16 h0 = __float2bfloat16(v.x), h1 = __float2bfloat16(v.y);
    __nv_bfloat16 h2 = __float2bfloat16(v.z), h3 = __float2bfloat16(v.w);
    __nv_bfloat16 l0 = __float2bfloat16(v.x - __bfloat162float(h0));
    __nv_bfloat16 l1 = __float2bfloat16(v.y - __bfloat162float(h1));
    __nv_bfloat16 l2 = __float2bfloat16(v.z - __bfloat162float(h2));
    __nv_bfloat16 l3 = __float2bfloat16(v.w - __bfloat162float(h3));
    __nv_bfloat162 hp0 = __halves2bfloat162(h0, h1), hp1 = __halves2bfloat162(h2, h3);
    __nv_bfloat162 lp0 = __halves2bfloat162(l0, l1), lp1 = __halves2bfloat162(l2, l3);
    hi = make_uint2(*(uint32_t*)&hp0, *(uint32_t*)&hp1);
    lo = make_uint2(*(uint32_t*)&lp0, *(uint32_t*)&lp1);
}

#define PITCH   144
#define A_H_OFF 0
#define A_L_OFF 9216
#define B_H_OFF 18432
#define B_L_OFF 27648
#define TILE_SMEM 36864

__device__ __forceinline__ void store_pair(char* sm, int base_h, int base_l,
                                           int row, int c4, float4 v) {
    uint2 hi, lo;
    cvt_hl(v, hi, lo);
    *(uint2*)(sm + base_h + row * PITCH + c4 * 8) = hi;
    *(uint2*)(sm + base_l + row * PITCH + c4 * 8) = lo;
}

// 64-K tile compute, 8 warps: warp tile 16x32.
__device__ __forceinline__ void mma_tile64_8w(uint32_t sb, int wm, int wn, int lane,
                                              float acc[4][4]) {
    #pragma unroll
    for (int ks = 0; ks < 4; ks++) {
        uint32_t a_h[4], a_l[4], b_h[4][2], b_l[4][2];
        {
            uint32_t r  = wm + (lane & 15);
            uint32_t cb = ks * 32 + ((lane >> 4) << 4);
            ldsm4(a_h, sb + A_H_OFF + r * PITCH + cb);
            ldsm4(a_l, sb + A_L_OFF + r * PITCH + cb);
        }
        #pragma unroll
        for (int g = 0; g < 2; g++) {
            uint32_t n  = wn + g * 16 + (lane & 7) + (((lane >> 4) & 1) << 3);
            uint32_t cb = ks * 32 + (((lane >> 3) & 1) << 4);
            uint32_t t[4];
            ldsm4(t, sb + B_H_OFF + n * PITCH + cb);
            b_h[g*2][0] = t[0]; b_h[g*2][1] = t[1];
            b_h[g*2+1][0] = t[2]; b_h[g*2+1][1] = t[3];
            ldsm4(t, sb + B_L_OFF + n * PITCH + cb);
            b_l[g*2][0] = t[0]; b_l[g*2][1] = t[1];
            b_l[g*2+1][0] = t[2]; b_l[g*2+1][1] = t[3];
        }
        #pragma unroll
        for (int ni = 0; ni < 4; ni++) {
            mma16816(acc[ni], a_h, b_h[ni]);
            mma16816(acc[ni], a_h, b_l[ni]);
            mma16816(acc[ni], a_l, b_h[ni]);
        }
    }
}

// generic NT tile GEMM core (64x64 CTA tile)
__device__ __forceinline__ void hmma_tile_core(
    char* sm, uint32_t sb, int tid,
    const float* __restrict__ A, const float* __restrict__ B,
    const float* __restrict__ bias, float* __restrict__ Cp,
    int bm, int bn, int kbase, int niter)
{
    const int wid = tid >> 5, lane = tid & 31;
    const int wm = (wid & 3) * 16, wn = (wid >> 2) * 32;

    float acc[4][4] = {};
    float4 pa[4], pb[4];
    #pragma unroll
    for (int j = 0; j < 4; j++) {
        int fid = tid + j * 256;
        int row = fid >> 4, c4 = fid & 15;
        pa[j] = *(const float4*)(A + (size_t)(bm + row) * E_SZ + kbase + c4 * 4);
        pb[j] = *(const float4*)(B + (size_t)(bn + row) * E_SZ + kbase + c4 * 4);
    }
    for (int it = 0; it < niter; it++) {
        #pragma unroll
        for (int j = 0; j < 4; j++) {
            int fid = tid + j * 256;
            int row = fid >> 4, c4 = fid & 15;
            store_pair(sm, A_H_OFF, A_L_OFF, row, c4, pa[j]);
            store_pair(sm, B_H_OFF, B_L_OFF, row, c4, pb[j]);
        }
        __syncthreads();
        if (it + 1 < niter) {
            int k0 = kbase + (it + 1) * 64;
            #pragma unroll
            for (int j = 0; j < 4; j++) {
                int fid = tid + j * 256;
                int row = fid >> 4, c4 = fid & 15;
                pa[j] = *(const float4*)(A + (size_t)(bm + row) * E_SZ + k0 + c4 * 4);
                pb[j] = *(const float4*)(B + (size_t)(bn + row) * E_SZ + k0 + c4 * 4);
            }
        }
        mma_tile64_8w(sb, wm, wn, lane, acc);
        __syncthreads();
    }
    {
        int r0 = bm + wm + (lane >> 2);
        #pragma unroll
        for (int ni = 0; ni < 4; ni++) {
            int c0 = bn + wn + ni * 8 + (lane & 3) * 2;
            float bb0 = bias ? bias[c0] : 0.f;
            float bb1 = bias ? bias[c0 + 1] : 0.f;
            *(float2*)(Cp + (size_t)r0 * E_SZ + c0) =
                make_float2(acc[ni][0] + bb0, acc[ni][1] + bb1);
            *(float2*)(Cp + (size_t)(r0 + 8) * E_SZ + c0) =
                make_float2(acc[ni][2] + bb0, acc[ni][3] + bb1);
        }
    }
}

// ---------------------------------------------------------------
// gather one (b,p) point; 192 active lanes of a 256-thread block
// ---------------------------------------------------------------
__device__ __forceinline__ void gather_point(
    int bp, int t,
    const float* __restrict__ x,
    const float* __restrict__ bc,
    const float* __restrict__ off,
    float* __restrict__ S)
{
    if (t >= 192) return;
    const int b = bp >> 5, p = bp & 31;

    float cx = fminf(fmaxf(bc[p*3+0] + off[bp*3+0], -1.f), 1.f);
    float cy = fminf(fmaxf(bc[p*3+1] + off[bp*3+1], -1.f), 1.f);
    float cz = fminf(fmaxf(bc[p*3+2] + off[bp*3+2], -1.f), 1.f);

    float ix = (cx + 1.0f) * 0.5f * (GRIDSZ - 1);
    float iy = (cy + 1.0f) * 0.5f * (GRIDSZ - 1);
    float iz = (cz + 1.0f) * 0.5f * (GRIDSZ - 1);

    float fx = floorf(ix), fy = floorf(iy), fz = floorf(iz);
    float wx = ix - fx, wy = iy - fy, wz = iz - fz;

    int x0 = min(max((int)fx, 0), GRIDSZ-1);
    int y0 = min(max((int)fy, 0), GRIDSZ-1);
    int z0 = min(max((int)fz, 0), GRIDSZ-1);
    int x1 = min(x0 + 1, GRIDSZ-1);
    int y1 = min(y0 + 1, GRIDSZ-1);
    int z1 = min(z0 + 1, GRIDSZ-1);

    const float* xb = x + ((size_t)b * FULLN + 1) * E_SZ;

    int idx[8];
    idx[0] = (((z0*GRIDSZ)+y0)*GRIDSZ + x0) * E_SZ;
    idx[1] = (((z0*GRIDSZ)+y0)*GRIDSZ + x1) * E_SZ;
    idx[2] = (((z0*GRIDSZ)+y1)*GRIDSZ + x0) * E_SZ;
    idx[3] = (((z0*GRIDSZ)+y1)*GRIDSZ + x1) * E_SZ;
    idx[4] = (((z1*GRIDSZ)+y0)*GRIDSZ + x0) * E_SZ;
    idx[5] = (((z1*GRIDSZ)+y0)*GRIDSZ + x1) * E_SZ;
    idx[6] = (((z1*GRIDSZ)+y1)*GRIDSZ + x0) * E_SZ;
    idx[7] = (((z1*GRIDSZ)+y1)*GRIDSZ + x1) * E_SZ;

    float w[8];
    w[0] = (1-wz)*(1-wy)*(1-wx);
    w[1] = (1-wz)*(1-wy)*wx;
    w[2] = (1-wz)*wy*(1-wx);
    w[3] = (1-wz)*wy*wx;
    w[4] = wz*(1-wy)*(1-wx);
    w[5] = wz*(1-wy)*wx;
    w[6] = wz*wy*(1-wx);
    w[7] = wz*wy*wx;

    float4* outv = (float4*)(S + (size_t)bp * E_SZ);
    float4 acc = make_float4(0.f,0.f,0.f,0.f);
    #pragma unroll
    for (int i = 0; i < 8; i++) {
        float4 v = ((const float4*)(xb + idx[i]))[t];
        acc.x = fmaf(w[i], v.x, acc.x);
        acc.y = fmaf(w[i], v.y, acc.y);
        acc.z = fmaf(w[i], v.z, acc.z);
        acc.w = fmaf(w[i], v.w, acc.w);
    }
    outv[t] = acc;
}

// ---------------------------------------------------------------
// k1: qproj (48) | transposes (1152) | bias2 (12)
// ---------------------------------------------------------------
#define K1_QPROJ 48
#define K1_TRANS 1152
#define K1_GRID  (K1_QPROJ + K1_TRANS + 12)

__global__ __launch_bounds__(256)
void k1_front(const float* __restrict__ bio,
              const float* __restrict__ in_proj_w,
              const float* __restrict__ sample_w,
              const float* __restrict__ sample_b,
              float* __restrict__ P1,
              float* __restrict__ WsT,
              float* __restrict__ WkT,
              float* __restrict__ B2)
{
    __shared__ __align__(16) char sm[TILE_SMEM];
    const int bid = blockIdx.x;
    const int t   = threadIdx.x;

    if (bid < K1_QPROJ) {
        const int n = bid % 12, z = bid / 12;
        hmma_tile_core(sm, smem_u32(sm), t, bio, in_proj_w, nullptr,
                       P1 + (size_t)z * B_SZ * E_SZ, 0, n * 64, z * 192, 3);
    } else if (bid < K1_QPROJ + K1_TRANS) {
        int tb = bid - K1_QPROJ;
        const int zsel = tb / 576; tb -= zsel * 576;
        const int bx = (tb % 24) * 32, by = (tb / 24) * 32;
        const float* A = zsel ? (in_proj_w + (size_t)E_SZ * E_SZ) : sample_w;
        float* At      = zsel ? WkT : WsT;
        float (*ts)[33] = (float(*)[33])sm;
        const int tx = t & 31, ty = t >> 5;
        #pragma unroll
        for (int i = 0; i < 32; i += 8)
            ts[ty + i][tx] = A[(size_t)(by + ty + i) * E_SZ + bx + tx];
        __syncthreads();
        #pragma unroll
        for (int i = 0; i < 32; i += 8)
            At[(size_t)(bx + ty + i) * E_SZ + by + tx] = ts[tx][ty + i];
    } else {
        // bias2[r] = sum_k sample_b[k] * Wv[r,k], 64 rows per CTA
        const int h = bid - (K1_QPROJ + K1_TRANS);
        const int w = t >> 5, lane = t & 31;
        const float* Wv = in_proj_w + (size_t)2 * E_SZ * E_SZ;
        #pragma unroll
        for (int i = 0; i < 8; i++) {
            int r = h * 64 + w * 8 + i;
            float acc = 0.f;
            #pragma unroll
            for (int j = 0; j < 24; j++) {
                int k = lane + j * 32;
                acc = fmaf(sample_b[k], Wv[(size_t)r * E_SZ + k], acc);
            }
            #pragma unroll
            for (int o = 16; o; o >>= 1) acc += __shfl_xor_sync(0xffffffffu, acc, o);
            if (lane == 0) B2[r] = acc;
        }
    }
}

// ---------------------------------------------------------------
// Big NT GEMM body, CTA tile 128x64 (8 warps, warp tile 32x32)
// ---------------------------------------------------------------
#define BG_A_H 0
#define BG_A_L 18432
#define BG_B_H 36864
#define BG_B_L 46080
#define BG_SMEM 55296

__device__ __forceinline__ void big_nt_body(
    char* sm, int tid,
    const float* __restrict__ A, const float* __restrict__ B,
    float* __restrict__ PB, int bm, int bn, int z)
{
    const int wid = tid >> 5, lane = tid & 31;
    const int wm = (wid & 3) * 32, wn = (wid >> 2) * 32;
    const int kbase = z * 384;
    const uint32_t sb = smem_u32(sm);

    float acc[2][4][4] = {};
    float4 pa[8], pb[4];

    #pragma unroll
    for (int j = 0; j < 8; j++) {
        int fid = tid + j * 256;
        int row = fid >> 4, c4 = fid & 15;
        pa[j] = *(const float4*)(A + (size_t)(bm + row) * E_SZ + kbase + c4 * 4);
    }
    #pragma unroll
    for (int j = 0; j < 4; j++) {
        int fid = tid + j * 256;
        int row = fid >> 4, c4 = fid & 15;
        pb[j] = *(const float4*)(B + (size_t)(bn + row) * E_SZ + kbase + c4 * 4);
    }

    for (int it = 0; it < 6; it++) {
        #pragma unroll
        for (int j = 0; j < 8; j++) {
            int fid = tid + j * 256;
            int row = fid >> 4, c4 = fid & 15;
            store_pair(sm, BG_A_H, BG_A_L, row, c4, pa[j]);
        }
        #pragma unroll
        for (int j = 0; j < 4; j++) {
            int fid = tid + j * 256;
            int row = fid >> 4, c4 = fid & 15;
            store_pair(sm, BG_B_H, BG_B_L, row, c4, pb[j]);
        }
        __syncthreads();
        if (it + 1 < 6) {
            int k0 = kbase + (it + 1) * 64;
            #pragma unroll
            for (int j = 0; j < 8; j++) {
                int fid = tid + j * 256;
                int row = fid >> 4, c4 = fid & 15;
                pa[j] = *(const float4*)(A + (size_t)(bm + row) * E_SZ + k0 + c4 * 4);
            }
            #pragma unroll
            for (int j = 0; j < 4; j++) {
                int fid = tid + j * 256;
                int row = fid >> 4, c4 = fid & 15;
                pb[j] = *(const float4*)(B + (size_t)(bn + row) * E_SZ + k0 + c4 * 4);
            }
        }
        #pragma unroll
        for (int ks = 0; ks < 4; ks++) {
            uint32_t a_h[2][4], a_l[2][4], b_h[4][2], b_l[4][2];
            #pragma unroll
            for (int mi = 0; mi < 2; mi++) {
                uint32_t r  = wm + mi * 16 + (lane & 15);
                uint32_t cb = ks * 32 + ((lane >> 4) << 4);
                ldsm4(a_h[mi], sb + BG_A_H + r * PITCH + cb);
                ldsm4(a_l[mi], sb + BG_A_L + r * PITCH + cb);
            }
            #pragma unroll
            for (int g = 0; g < 2; g++) {
                uint32_t n  = wn + g * 16 + (lane & 7) + (((lane >> 4) & 1) << 3);
                uint32_t cb = ks * 32 + (((lane >> 3) & 1) << 4);
                uint32_t t[4];
                ldsm4(t, sb + BG_B_H + n * PITCH + cb);
                b_h[g*2][0] = t[0]; b_h[g*2][1] = t[1];
                b_h[g*2+1][0] = t[2]; b_h[g*2+1][1] = t[3];
                ldsm4(t, sb + BG_B_L + n * PITCH + cb);
                b_l[g*2][0] = t[0]; b_l[g*2][1] = t[1];
                b_l[g*2+1][0] = t[2]; b_l[g*2+1][1] = t[3];
            }
            #pragma unroll
            for (int mi = 0; mi < 2; mi++)
                #pragma unroll
                for (int ni = 0; ni < 4; ni++) {
                    mma16816(acc[mi][ni], a_h[mi], b_h[ni]);
                    mma16816(acc[mi][ni], a_h[mi], b_l[ni]);
                    mma16816(acc[mi][ni], a_l[mi], b_h[ni]);
                }
        }
        __syncthreads();
    }

    float* Cp = PB + (size_t)z * E_SZ * E_SZ;
    #pragma unroll
    for (int mi = 0; mi < 2; mi++) {
        int r0 = bm + wm + mi * 16 + (lane >> 2);
        #pragma unroll
        for (int ni = 0; ni < 4; ni++) {
            int c0 = bn + wn + ni * 8 + (lane & 3) * 2;
            *(float2*)(Cp + (size_t)r0 * E_SZ + c0) =
                make_float2(acc[mi][ni][0], acc[mi][ni][1]);
            *(float2*)(Cp + (size_t)(r0 + 8) * E_SZ + c0) =
                make_float2(acc[mi][ni][2], acc[mi][ni][3]);
        }
    }
}

// ---------------------------------------------------------------
// k2: thead (144) | WV gemm z=0 (72) | gather half 1 (1024)
// ---------------------------------------------------------------
#define K2_THEAD 144
#define K2_WV    72
#define K2_GRID  (K2_THEAD + K2_WV + 1024)

__global__ __launch_bounds__(256)
void k2_thead_gather(const float* __restrict__ P1,
                     const float* __restrict__ in_proj_b,
                     const float* __restrict__ WkT,
                     const float* __restrict__ in_proj_w,
                     const float* __restrict__ WsT,
                     float* __restrict__ T,
                     float* __restrict__ WV,
                     const float* __restrict__ x,
                     const float* __restrict__ bc,
                     const float* __restrict__ off,
                     float* __restrict__ S)
{
    __shared__ __align__(16) char sm[BG_SMEM];
    const int bid = blockIdx.x;
    const int tid = threadIdx.x;

    if (bid >= K2_THEAD + K2_WV) {
        gather_point(bid - (K2_THEAD + K2_WV), tid, x, bc, off, S);
        return;
    }
    if (bid >= K2_THEAD) {
        // M = Wv @ Ws: NT with A = Wv rows, B = WsT rows. K-half z=0.
        int wb = bid - K2_THEAD;
        int n = wb % 12, m = wb / 12;
        big_nt_body(sm, tid, in_proj_w + (size_t)2 * E_SZ * E_SZ, WsT,
                    WV, m * 128, n * 64, 0);
        return;
    }

    const int wid  = tid >> 5, lane = tid & 31;
    const int e0   = (bid % 12) * 64;
    const int h    = bid / 12;
    const int wm   = (wid & 3) * 16, wn = (wid >> 2) * 32;
    const uint32_t sb = smem_u32(sm);

    #pragma unroll
    for (int j = 0; j < 4; j++) {
        int fid = tid + j * 256;
        int row = fid >> 4, c4 = fid & 15;
        const float* pbase = P1 + (size_t)row * E_SZ + h * 64 + c4 * 4;
        float4 v = *(const float4*)pbase;
        #pragma unroll
        for (int s = 1; s < 4; s++) {
            float4 p = *(const float4*)(pbase + (size_t)s * B_SZ * E_SZ);
            v.x += p.x; v.y += p.y; v.z += p.z; v.w += p.w;
        }
        float4 bq = *(const float4*)(in_proj_b + h * 64 + c4 * 4);
        v.x += bq.x; v.y += bq.y; v.z += bq.z; v.w += bq.w;
        store_pair(sm, A_H_OFF, A_L_OFF, row, c4, v);
        float4 vb = *(const float4*)(WkT + (size_t)(e0 + row) * E_SZ + h * 64 + c4 * 4);
        store_pair(sm, B_H_OFF, B_L_OFF, row, c4, vb);
    }
    __syncthreads();

    float acc[4][4] = {};
    mma_tile64_8w(sb, wm, wn, lane, acc);

    {
        int r0 = h * 64 + wm + (lane >> 2);
        #pragma unroll
        for (int ni = 0; ni < 4; ni++) {
            int c0 = e0 + wn + ni * 8 + (lane & 3) * 2;
            *(float2*)(T + (size_t)r0 * E_SZ + c0) = make_float2(acc[ni][0], acc[ni][1]);
            *(float2*)(T + (size_t)(r0 + 8) * E_SZ + c0) = make_float2(acc[ni][2], acc[ni][3]);
        }
    }
}

// ---------------------------------------------------------------
// k3: gemm1 (144) | WV gemm z=1 (72) | gather half 2 (1024)
// ---------------------------------------------------------------
#define K3_GEMM 144
#define K3_WV   72
#define K3_GRID (K3_GEMM + K3_WV + 1024)

__global__ __launch_bounds__(256)
void k3_gemm1_gather(const float* __restrict__ T,
                     const float* __restrict__ WsT,
                     const float* __restrict__ in_proj_w,
                     float* __restrict__ PB,
                     float* __restrict__ WV,
                     const float* __restrict__ x,
                     const float* __restrict__ bc,
                     const float* __restrict__ off,
                     float* __restrict__ S)
{
    __shared__ __align__(16) char sm[BG_SMEM];
    const int bid = blockIdx.x;
    const int tid = threadIdx.x;

    if (bid >= K3_GEMM + K3_WV) {
        gather_point(1024 + (bid - (K3_GEMM + K3_WV)), tid, x, bc, off, S);
        return;
    }
    if (bid >= K3_GEMM) {
        int wb = bid - K3_GEMM;
        int n = wb % 12, m = wb / 12;
        big_nt_body(sm, tid, in_proj_w + (size_t)2 * E_SZ * E_SZ, WsT,
                    WV, m * 128, n * 64, 1);
        return;
    }
    const int n = bid % 12;
    const int rest = bid / 12;
    const int m = rest % 6, z = rest / 6;
    big_nt_body(sm, tid, T, WsT, PB, m * 128, n * 64, z);
}

// ---------------------------------------------------------------
// Fused attention (R12 proven config): grid (64 b, 2 halves of 6), 512 thr.
// ---------------------------------------------------------------
#define HGRP 6
__global__ __launch_bounds__(512)
void attn_fuse_kernel(const float* __restrict__ QHp,
                      const float* __restrict__ S,
                      float* __restrict__ WS)
{
    extern __shared__ float smf[];
    float* Ssm = smf;
    float* qsm = smf + NB * E_SZ;
    float* sc  = qsm + HGRP * E_SZ;
    float* at  = sc + HGRP * NB;

    const int b  = blockIdx.x;
    const int h0 = blockIdx.y * HGRP;
    const int t  = threadIdx.x;
    const int w = t >> 5, lane = t & 31;

    {
        const float4* src = (const float4*)(S + (size_t)b * NB * E_SZ);
        float4* dst = (float4*)Ssm;
        #pragma unroll
        for (int i = t; i < NB * E_SZ / 4; i += 512) dst[i] = src[i];
        float4* qdst = (float4*)qsm;
        for (int i = t; i < HGRP * E_SZ / 4; i += 512) {
            int hl = i / 192, c4 = i - hl * 192;
            const float4* q0 = (const float4*)(QHp + (size_t)((h0 + hl) * 64 + b) * E_SZ) + c4;
            float4 v0 = *q0;
            float4 v1 = *(const float4*)((const float*)q0 + (size_t)E_SZ * E_SZ);
            v0.x += v1.x; v0.y += v1.y; v0.z += v1.z; v0.w += v1.w;
            qdst[i] = v0;
        }
    }
    __syncthreads();

    if (w < 12) {
        const int hp = w >> 2, pg = w & 3;
        const int ha = hp * 2, hb = ha + 1;
        float qa[24], qb[24];
        #pragma unroll
        for (int i = 0; i < 24; i++) {
            qa[i] = qsm[ha * E_SZ + lane + i * 32];
            qb[i] = qsm[hb * E_SZ + lane + i * 32];
        }
        #pragma unroll
        for (int p = 0; p < 8; p++) {
            const int pp = pg * 8 + p;
            const float* sr = Ssm + pp * E_SZ;
            float acca = 0.f, accb = 0.f;
            #pragma unroll
            for (int i = 0; i < 24; i++) {
                float sv = sr[lane + i * 32];
                acca = fmaf(qa[i], sv, acca);
                accb = fmaf(qb[i], sv, accb);
            }
            #pragma unroll
            for (int o = 16; o; o >>= 1) {
                acca += __shfl_xor_sync(0xffffffffu, acca, o);
                accb += __shfl_xor_sync(0xffffffffu, accb, o);
            }
            if (lane == 0) {
                sc[ha * 32 + pp] = acca * 0.125f;
                sc[hb * 32 + pp] = accb * 0.125f;
            }
        }
    }
    __syncthreads();

    if (w < HGRP) {
        float s = sc[w*32 + lane];
        float m = s;
        #pragma unroll
        for (int o = 16; o; o >>= 1) m = fmaxf(m, __shfl_xor_sync(0xffffffffu, m, o));
        float e = __expf(s - m);
        float sum = e;
        #pragma unroll
        for (int o = 16; o; o >>= 1) sum += __shfl_xor_sync(0xffffffffu, sum, o);
        at[w*32 + lane] = e / sum;
    }
    __syncthreads();

    if (w < 12) {
        const int hp = w >> 2, cg = w & 3;
        const int ha = hp * 2, hb = ha + 1;
        float ata[32], atb[32];
        #pragma unroll
        for (int p = 0; p < 32; p++) {
            ata[p] = at[ha * 32 + p];
            atb[p] = at[hb * 32 + p];
        }
        float* wrow_a = WS + (size_t)((h0 + ha) * 64 + b) * E_SZ;
        float* wrow_b = WS + (size_t)((h0 + hb) * 64 + b) * E_SZ;
        #pragma unroll
        for (int j = 0; j < 6; j++) {
            const int c = cg * 192 + j * 32 + lane;
            float acca = 0.f, accb = 0.f;
            #pragma unroll
            for (int p = 0; p < 32; p++) {
                float sv = Ssm[p * E_SZ + c];
                acca = fmaf(ata[p], sv, acca);
                accb = fmaf(atb[p], sv, accb);
            }
            wrow_a[c] = acca;
            wrow_b[c] = accb;
        }
    }
}

// ---------------------------------------------------------------
// ctx2 HMMA: P2[(h*4+s)] = WS_h @ (WV0+WV1)_h^T   grid (1,12,4), K chunk 192
// ---------------------------------------------------------------
__global__ __launch_bounds__(256)
void ctx2_hmma(const float* __restrict__ WS,
               const float* __restrict__ WV,
               float* __restrict__ P2)
{
    __shared__ __align__(16) char sm[TILE_SMEM];
    const int tid  = threadIdx.x;
    const int wid  = tid >> 5, lane = tid & 31;
    const int h    = blockIdx.y, s = blockIdx.z;
    const int wm   = (wid & 3) * 16, wn = (wid >> 2) * 32;
    const uint32_t sb = smem_u32(sm);

    float acc[4][4] = {};
    for (int it = 0; it < 3; it++) {
        int k0 = s * 192 + it * 64;
        #pragma unroll
        for (int j = 0; j < 4; j++) {
            int fid = tid + j * 256;
            int row = fid >> 4, c4 = fid & 15;
            float4 va = *(const float4*)(WS + (size_t)(h * 64 + row) * E_SZ + k0 + c4 * 4);
            store_pair(sm, A_H_OFF, A_L_OFF, row, c4, va);
            const float* wb = WV + (size_t)(h * 64 + row) * E_SZ + k0 + c4 * 4;
            float4 vb = *(const float4*)wb;
            float4 v1 = *(const float4*)(wb + (size_t)E_SZ * E_SZ);
            vb.x += v1.x; vb.y += v1.y; vb.z += v1.z; vb.w += v1.w;
            store_pair(sm, B_H_OFF, B_L_OFF, row, c4, vb);
        }
        __syncthreads();
        mma_tile64_8w(sb, wm, wn, lane, acc);
        __syncthreads();
    }

    float* Pp = P2 + (size_t)(h * 4 + s) * 4096;
    {
        int r0 = wm + (lane >> 2);
        #pragma unroll
        for (int ni = 0; ni < 4; ni++) {
            int c0 = wn + ni * 8 + (lane & 3) * 2;
            *(float2*)(Pp + r0 * 64 + c0) = make_float2(acc[ni][0], acc[ni][1]);
            *(float2*)(Pp + (r0 + 8) * 64 + c0) = make_float2(acc[ni][2], acc[ni][3]);
        }
    }
}

// ---------------------------------------------------------------
// out-proj HMMA partials (ctx reduce + bv + bias2 fused in A-loader)
// ---------------------------------------------------------------
__global__ __launch_bounds__(256)
void outproj_hmma(const float* __restrict__ P2,
                  const float* __restrict__ in_proj_b,
                  const float* __restrict__ B2,
                  const float* __restrict__ Wo,
                  float* __restrict__ P1)
{
    __shared__ __align__(16) char sm[TILE_SMEM];
    const int tid  = threadIdx.x;
    const int wid  = tid >> 5, lane = tid & 31;
    const int bn   = blockIdx.x * 64, s = blockIdx.z;
    const int wm   = (wid & 3) * 16, wn = (wid >> 2) * 32;
    const uint32_t sb = smem_u32(sm);

    float acc[4][4] = {};
    for (int it = 0; it < 3; it++) {
        int k0 = s * 192 + it * 64;
        int hh = k0 >> 6;
        #pragma unroll
        for (int j = 0; j < 4; j++) {
            int fid = tid + j * 256;
            int row = fid >> 4, c4 = fid & 15;
            const float* pbase = P2 + (size_t)(hh * 4) * 4096 + row * 64 + c4 * 4;
            float4 v = *(const float4*)pbase;
            #pragma unroll
            for (int ss = 1; ss < 4; ss++) {
                float4 p = *(const float4*)(pbase + (size_t)ss * 4096);
                v.x += p.x; v.y += p.y; v.z += p.z; v.w += p.w;
            }
            float4 bv = *(const float4*)(in_proj_b + 2 * E_SZ + k0 + c4 * 4);
            float4 b2 = *(const float4*)(B2 + k0 + c4 * 4);
            v.x += bv.x + b2.x; v.y += bv.y + b2.y;
            v.z += bv.z + b2.z; v.w += bv.w + b2.w;
            store_pair(sm, A_H_OFF, A_L_OFF, row, c4, v);
            float4 vb = *(const float4*)(Wo + (size_t)(bn + row) * E_SZ + k0 + c4 * 4);
            store_pair(sm, B_H_OFF, B_L_OFF, row, c4, vb);
        }
        __syncthreads();
        mma_tile64_8w(sb, wm, wn, lane, acc);
        __syncthreads();
    }

    float* Pp = P1 + (size_t)s * B_SZ * E_SZ;
    {
        int r0 = wm + (lane >> 2);
        #pragma unroll
        for (int ni = 0; ni < 4; ni++) {
            int c0 = bn + wn + ni * 8 + (lane & 3) * 2;
            *(float2*)(Pp + (size_t)r0 * E_SZ + c0) = make_float2(acc[ni][0], acc[ni][1]);
            *(float2*)(Pp + (size_t)(r0 + 8) * E_SZ + c0) = make_float2(acc[ni][2], acc[ni][3]);
        }
    }
}

// ---------------------------------------------------------------
// Fused reduce + broadcast
// ---------------------------------------------------------------
__global__ __launch_bounds__(256)
void bcast_reduce_kernel(const float* __restrict__ P1,
                         const float* __restrict__ bo,
                         const float* __restrict__ conf,
                         float* __restrict__ out)
{
    __shared__ __align__(16) float ao[E_SZ];
    const int b  = blockIdx.x;
    const int n0 = blockIdx.y * 27;
    const int t  = threadIdx.x;
    const float cf = conf[b];

    for (int c = t; c < E_SZ; c += 256) {
        float a0 = P1[(size_t)b * E_SZ + c];
        float a1 = P1[(size_t)(B_SZ + b) * E_SZ + c];
        float a2 = P1[(size_t)(2 * B_SZ + b) * E_SZ + c];
        float a3 = P1[(size_t)(3 * B_SZ + b) * E_SZ + c];
        ao[c] = ((a0 + a1) + (a2 + a3) + bo[c]) * cf;
    }
    __syncthreads();

    const float4* src = (const float4*)ao;
    float4* dstb = (float4*)(out + ((size_t)b * FULLN + n0) * E_SZ);
    const int nrows = min(27, FULLN - n0);
    for (int i = t; i < nrows * 192; i += 256) {
        int r = i / 192, c = i - r * 192;
        dstb[(size_t)r * 192 + c] = src[c];
    }
}

// ---------------------------------------------------------------
extern "C" void kernel_launch(void* const* d_in, const int* in_sizes, int n_in,
                              void* d_out, int out_size)
{
    const float* x           = (const float*)d_in[0];
    const float* bio_embed   = (const float*)d_in[1];
    const float* base_coords = (const float*)d_in[2];
    const float* offsets     = (const float*)d_in[3];
    const float* confidence  = (const float*)d_in[4];
    const float* sample_w    = (const float*)d_in[5];
    const float* sample_b    = (const float*)d_in[6];
    const float* in_proj_w   = (const float*)d_in[7];
    const float* in_proj_b   = (const float*)d_in[8];
    const float* out_proj_w  = (const float*)d_in[9];
    const float* out_proj_b  = (const float*)d_in[10];
    float* out = (float*)d_out;

    float *S, *T, *WS, *P1, *P2, *PB, *WV, *B2, *WsT, *WkT;
    cudaGetSymbolAddress((void**)&S,   g_S);
    cudaGetSymbolAddress((void**)&T,   g_T);
    cudaGetSymbolAddress((void**)&WS,  g_WS);
    cudaGetSymbolAddress((void**)&P1,  g_P1);
    cudaGetSymbolAddress((void**)&P2,  g_P2);
    cudaGetSymbolAddress((void**)&PB,  g_PB);
    cudaGetSymbolAddress((void**)&WV,  g_WV);
    cudaGetSymbolAddress((void**)&B2,  g_B2);
    cudaGetSymbolAddress((void**)&WsT, g_WsT);
    cudaGetSymbolAddress((void**)&WkT, g_WkT);

    const int attn_smem = (NB * E_SZ + HGRP * E_SZ + 2 * HGRP * NB) * sizeof(float);
    cudaFuncSetAttribute(attn_fuse_kernel,
                         cudaFuncAttributeMaxDynamicSharedMemorySize, attn_smem);

    // 1) qproj partials + both transposes + bias2
    k1_front<<<K1_GRID, 256>>>(bio_embed, in_proj_w, sample_w, sample_b,
                               P1, WsT, WkT, B2);

    // 2) thead + WV z=0 + gather half 1
    k2_thead_gather<<<K2_GRID, 256>>>(P1, in_proj_b, WkT, in_proj_w, WsT,
                                      T, WV, x, base_coords, offsets, S);

    // 3) QH partials + WV z=1 + gather half 2
    k3_gemm1_gather<<<K3_GRID, 256>>>(T, WsT, in_proj_w, PB, WV,
                                      x, base_coords, offsets, S);

    // 4) fused scores + softmax + weighted-S
    attn_fuse_kernel<<<dim3(B_SZ, 2), 512, attn_smem>>>(PB, S, WS);

    // 5) ctx partials: WS_h @ (WV0+WV1)_h^T
    ctx2_hmma<<<dim3(1, 12, 4), 256>>>(WS, WV, P2);

    // 6) out-proj partials (fused ctx reduce + bv + bias2)
    outproj_hmma<<<dim3(12, 1, 4), 256>>>(P2, in_proj_b, B2, out_proj_w, P1);

    // 7) fused reduce + broadcast * confidence
    bcast_reduce_kernel<<<dim3(B_SZ, 19), 256>>>(P1, out_proj_b, confidence, out);
}

// round 16
// speedup vs baseline: 1.1736x; 1.1030x over previous
#include <cuda_runtime.h>
#include <cuda_bf16.h>
#include <math.h>
#include <stdint.h>

#define B_SZ   64
#define FULLN  513
#define E_SZ   768
#define NB     32
#define GRIDSZ 8
#define NHEAD  12
#define HDIM   64
#define NP     (B_SZ * NB)      // 2048

// ---------------- scratch (device globals) ----------------
__device__ float g_S  [NP * E_SZ];
__device__ float g_T  [E_SZ * E_SZ];
__device__ float g_WS [E_SZ * E_SZ];
__device__ float g_P1 [4 * B_SZ * E_SZ];
__device__ float g_P2 [12 * 4 * 64 * 64];
__device__ float g_PB [2 * E_SZ * E_SZ];
__device__ float g_WsT[E_SZ * E_SZ];
__device__ float g_WkT[E_SZ * E_SZ];
__device__ int   g_bar_count;
__device__ int   g_bar_gen;

// ================= tensor-core helpers =================
__device__ __forceinline__ uint32_t smem_u32(const void* p) {
    uint32_t a;
    asm("{ .reg .u64 t; cvta.to.shared.u64 t, %1; cvt.u32.u64 %0, t; }" : "=r"(a) : "l"(p));
    return a;
}
__device__ __forceinline__ void ldsm4(uint32_t* r, uint32_t addr) {
    asm volatile("ldmatrix.sync.aligned.m8n8.x4.shared.b16 {%0,%1,%2,%3}, [%4];"
        : "=r"(r[0]), "=r"(r[1]), "=r"(r[2]), "=r"(r[3]) : "r"(addr));
}
__device__ __forceinline__ void mma16816(float* d, const uint32_t* a, const uint32_t* b) {
    asm volatile("mma.sync.aligned.m16n8k16.row.col.f32.bf16.bf16.f32 "
        "{%0,%1,%2,%3}, {%4,%5,%6,%7}, {%8,%9}, {%0,%1,%2,%3};"
        : "+f"(d[0]), "+f"(d[1]), "+f"(d[2]), "+f"(d[3])
        : "r"(a[0]), "r"(a[1]), "r"(a[2]), "r"(a[3]), "r"(b[0]), "r"(b[1]));
}
__device__ __forceinline__ void cvt_hl(float4 v, uint2& hi, uint2& lo) {
    __nv_bfloat16 h0 = __float2bfloat16(v.x), h1 = __float2bfloat16(v.y);
    __nv_bfloat16 h2 = __float2bfloat16(v.z), h3 = __float2bfloat16(v.w);
    __nv_bfloat16 l0 = __float2bfloat16(v.x - __bfloat162float(h0));
    __nv_bfloat16 l1 = __float2bfloat16(v.y - __bfloat162float(h1));
    __nv_bfloat16 l2 = __float2bfloat16(v.z - __bfloat162float(h2));
    __nv_bfloat16 l3 = __float2bfloat16(v.w - __bfloat162float(h3));
    __nv_bfloat162 hp0 = __halves2bfloat162(h0, h1), hp1 = __halves2bfloat162(h2, h3);
    __nv_bfloat162 lp0 = __halves2bfloat162(l0, l1), lp1 = __halves2bfloat162(l2, l3);
    hi = make_uint2(*(uint32_t*)&hp0, *(uint32_t*)&hp1);
    lo = make_uint2(*(uint32_t*)&lp0, *(uint32_t*)&lp1);
}

#define PITCH   144
#define A_H_OFF 0
#define A_L_OFF 9216
#define B_H_OFF 18432
#define B_L_OFF 27648
#define TILE_SMEM 36864

__device__ __forceinline__ void store_pair(char* sm, int base_h, int base_l,
                                           int row, int c4, float4 v) {
    uint2 hi, lo;
    cvt_hl(v, hi, lo);
    *(uint2*)(sm + base_h + row * PITCH + c4 * 8) = hi;
    *(uint2*)(sm + base_l + row * PITCH + c4 * 8) = lo;
}

// 64-K tile compute, 8 warps: warp tile 16x32.
__device__ __forceinline__ void mma_tile64_8w(uint32_t sb, int wm, int wn, int lane,
                                              float acc[4][4]) {
    #pragma unroll
    for (int ks = 0; ks < 4; ks++) {
        uint32_t a_h[4], a_l[4], b_h[4][2], b_l[4][2];
        {
            uint32_t r  = wm + (lane & 15);
            uint32_t cb = ks * 32 + ((lane >> 4) << 4);
            ldsm4(a_h, sb + A_H_OFF + r * PITCH + cb);
            ldsm4(a_l, sb + A_L_OFF + r * PITCH + cb);
        }
        #pragma unroll
        for (int g = 0; g < 2; g++) {
            uint32_t n  = wn + g * 16 + (lane & 7) + (((lane >> 4) & 1) << 3);
            uint32_t cb = ks * 32 + (((lane >> 3) & 1) << 4);
            uint32_t t[4];
            ldsm4(t, sb + B_H_OFF + n * PITCH + cb);
            b_h[g*2][0] = t[0]; b_h[g*2][1] = t[1];
            b_h[g*2+1][0] = t[2]; b_h[g*2+1][1] = t[3];
            ldsm4(t, sb + B_L_OFF + n * PITCH + cb);
            b_l[g*2][0] = t[0]; b_l[g*2][1] = t[1];
            b_l[g*2+1][0] = t[2]; b_l[g*2+1][1] = t[3];
        }
        #pragma unroll
        for (int ni = 0; ni < 4; ni++) {
            mma16816(acc[ni], a_h, b_h[ni]);
            mma16816(acc[ni], a_h, b_l[ni]);
            mma16816(acc[ni], a_l, b_h[ni]);
        }
    }
}

// generic NT tile GEMM core (64x64 CTA tile)
__device__ __forceinline__ void hmma_tile_core(
    char* sm, uint32_t sb, int tid,
    const float* __restrict__ A, const float* __restrict__ B,
    const float* __restrict__ bias, float* __restrict__ Cp,
    int bm, int bn, int kbase, int niter)
{
    const int wid = tid >> 5, lane = tid & 31;
    const int wm = (wid & 3) * 16, wn = (wid >> 2) * 32;

    float acc[4][4] = {};
    float4 pa[4], pb[4];
    #pragma unroll
    for (int j = 0; j < 4; j++) {
        int fid = tid + j * 256;
        int row = fid >> 4, c4 = fid & 15;
        pa[j] = *(const float4*)(A + (size_t)(bm + row) * E_SZ + kbase + c4 * 4);
        pb[j] = *(const float4*)(B + (size_t)(bn + row) * E_SZ + kbase + c4 * 4);
    }
    for (int it = 0; it < niter; it++) {
        #pragma unroll
        for (int j = 0; j < 4; j++) {
            int fid = tid + j * 256;
            int row = fid >> 4, c4 = fid & 15;
            store_pair(sm, A_H_OFF, A_L_OFF, row, c4, pa[j]);
            store_pair(sm, B_H_OFF, B_L_OFF, row, c4, pb[j]);
        }
        __syncthreads();
        if (it + 1 < niter) {
            int k0 = kbase + (it + 1) * 64;
            #pragma unroll
            for (int j = 0; j < 4; j++) {
                int fid = tid + j * 256;
                int row = fid >> 4, c4 = fid & 15;
                pa[j] = *(const float4*)(A + (size_t)(bm + row) * E_SZ + k0 + c4 * 4);
                pb[j] = *(const float4*)(B + (size_t)(bn + row) * E_SZ + k0 + c4 * 4);
            }
        }
        mma_tile64_8w(sb, wm, wn, lane, acc);
        __syncthreads();
    }
    {
        int r0 = bm + wm + (lane >> 2);
        #pragma unroll
        for (int ni = 0; ni < 4; ni++) {
            int c0 = bn + wn + ni * 8 + (lane & 3) * 2;
            float bb0 = bias ? bias[c0] : 0.f;
            float bb1 = bias ? bias[c0 + 1] : 0.f;
            *(float2*)(Cp + (size_t)r0 * E_SZ + c0) =
                make_float2(acc[ni][0] + bb0, acc[ni][1] + bb1);
            *(float2*)(Cp + (size_t)(r0 + 8) * E_SZ + c0) =
                make_float2(acc[ni][2] + bb0, acc[ni][3] + bb1);
        }
    }
}

// ---------------------------------------------------------------
// gather one (b,p) point; 192 active lanes of a 256-thread block
// ---------------------------------------------------------------
__device__ __forceinline__ void gather_point(
    int bp, int t,
    const float* __restrict__ x,
    const float* __restrict__ bc,
    const float* __restrict__ off,
    float* __restrict__ S)
{
    if (t >= 192) return;
    const int b = bp >> 5, p = bp & 31;

    float cx = fminf(fmaxf(bc[p*3+0] + off[bp*3+0], -1.f), 1.f);
    float cy = fminf(fmaxf(bc[p*3+1] + off[bp*3+1], -1.f), 1.f);
    float cz = fminf(fmaxf(bc[p*3+2] + off[bp*3+2], -1.f), 1.f);

    float ix = (cx + 1.0f) * 0.5f * (GRIDSZ - 1);
    float iy = (cy + 1.0f) * 0.5f * (GRIDSZ - 1);
    float iz = (cz + 1.0f) * 0.5f * (GRIDSZ - 1);

    float fx = floorf(ix), fy = floorf(iy), fz = floorf(iz);
    float wx = ix - fx, wy = iy - fy, wz = iz - fz;

    int x0 = min(max((int)fx, 0), GRIDSZ-1);
    int y0 = min(max((int)fy, 0), GRIDSZ-1);
    int z0 = min(max((int)fz, 0), GRIDSZ-1);
    int x1 = min(x0 + 1, GRIDSZ-1);
    int y1 = min(y0 + 1, GRIDSZ-1);
    int z1 = min(z0 + 1, GRIDSZ-1);

    const float* xb = x + ((size_t)b * FULLN + 1) * E_SZ;

    int idx[8];
    idx[0] = (((z0*GRIDSZ)+y0)*GRIDSZ + x0) * E_SZ;
    idx[1] = (((z0*GRIDSZ)+y0)*GRIDSZ + x1) * E_SZ;
    idx[2] = (((z0*GRIDSZ)+y1)*GRIDSZ + x0) * E_SZ;
    idx[3] = (((z0*GRIDSZ)+y1)*GRIDSZ + x1) * E_SZ;
    idx[4] = (((z1*GRIDSZ)+y0)*GRIDSZ + x0) * E_SZ;
    idx[5] = (((z1*GRIDSZ)+y0)*GRIDSZ + x1) * E_SZ;
    idx[6] = (((z1*GRIDSZ)+y1)*GRIDSZ + x0) * E_SZ;
    idx[7] = (((z1*GRIDSZ)+y1)*GRIDSZ + x1) * E_SZ;

    float w[8];
    w[0] = (1-wz)*(1-wy)*(1-wx);
    w[1] = (1-wz)*(1-wy)*wx;
    w[2] = (1-wz)*wy*(1-wx);
    w[3] = (1-wz)*wy*wx;
    w[4] = wz*(1-wy)*(1-wx);
    w[5] = wz*(1-wy)*wx;
    w[6] = wz*wy*(1-wx);
    w[7] = wz*wy*wx;

    float4* outv = (float4*)(S + (size_t)bp * E_SZ);
    float4 acc = make_float4(0.f,0.f,0.f,0.f);
    #pragma unroll
    for (int i = 0; i < 8; i++) {
        float4 v = ((const float4*)(xb + idx[i]))[t];
        acc.x = fmaf(w[i], v.x, acc.x);
        acc.y = fmaf(w[i], v.y, acc.y);
        acc.z = fmaf(w[i], v.z, acc.z);
        acc.w = fmaf(w[i], v.w, acc.w);
    }
    outv[t] = acc;
}

// ---------------------------------------------------------------
// k1: qproj (48) | transposes (1152)
// ---------------------------------------------------------------
#define K1_QPROJ 48
#define K1_GRID  (K1_QPROJ + 1152)

__global__ __launch_bounds__(256)
void k1_front(const float* __restrict__ bio,
              const float* __restrict__ in_proj_w,
              const float* __restrict__ sample_w,
              float* __restrict__ P1,
              float* __restrict__ WsT,
              float* __restrict__ WkT)
{
    __shared__ __align__(16) char sm[TILE_SMEM];
    const int bid = blockIdx.x;
    const int t   = threadIdx.x;

    if (bid < K1_QPROJ) {
        const int n = bid % 12, z = bid / 12;
        hmma_tile_core(sm, smem_u32(sm), t, bio, in_proj_w, nullptr,
                       P1 + (size_t)z * B_SZ * E_SZ, 0, n * 64, z * 192, 3);
    } else {
        int tb = bid - K1_QPROJ;
        const int zsel = tb / 576; tb -= zsel * 576;
        const int bx = (tb % 24) * 32, by = (tb / 24) * 32;
        const float* A = zsel ? (in_proj_w + (size_t)E_SZ * E_SZ) : sample_w;
        float* At      = zsel ? WkT : WsT;
        float (*ts)[33] = (float(*)[33])sm;
        const int tx = t & 31, ty = t >> 5;
        #pragma unroll
        for (int i = 0; i < 32; i += 8)
            ts[ty + i][tx] = A[(size_t)(by + ty + i) * E_SZ + bx + tx];
        __syncthreads();
        #pragma unroll
        for (int i = 0; i < 32; i += 8)
            At[(size_t)(bx + ty + i) * E_SZ + by + tx] = ts[tx][ty + i];
    }
}

// ---------------------------------------------------------------
// k2: thead (144) | gather half 1 (1024)
// ---------------------------------------------------------------
#define K2_THEAD 144
#define K2_GRID  (K2_THEAD + 1024)

__global__ __launch_bounds__(256)
void k2_thead_gather(const float* __restrict__ P1,
                     const float* __restrict__ in_proj_b,
                     const float* __restrict__ WkT,
                     float* __restrict__ T,
                     const float* __restrict__ x,
                     const float* __restrict__ bc,
                     const float* __restrict__ off,
                     float* __restrict__ S)
{
    __shared__ __align__(16) char sm[TILE_SMEM];
    const int bid = blockIdx.x;
    const int tid = threadIdx.x;

    if (bid >= K2_THEAD) {
        gather_point(bid - K2_THEAD, tid, x, bc, off, S);
        return;
    }

    const int wid  = tid >> 5, lane = tid & 31;
    const int e0   = (bid % 12) * 64;
    const int h    = bid / 12;
    const int wm   = (wid & 3) * 16, wn = (wid >> 2) * 32;
    const uint32_t sb = smem_u32(sm);

    #pragma unroll
    for (int j = 0; j < 4; j++) {
        int fid = tid + j * 256;
        int row = fid >> 4, c4 = fid & 15;
        const float* pbase = P1 + (size_t)row * E_SZ + h * 64 + c4 * 4;
        float4 v = *(const float4*)pbase;
        #pragma unroll
        for (int s = 1; s < 4; s++) {
            float4 p = *(const float4*)(pbase + (size_t)s * B_SZ * E_SZ);
            v.x += p.x; v.y += p.y; v.z += p.z; v.w += p.w;
        }
        float4 bq = *(const float4*)(in_proj_b + h * 64 + c4 * 4);
        v.x += bq.x; v.y += bq.y; v.z += bq.z; v.w += bq.w;
        store_pair(sm, A_H_OFF, A_L_OFF, row, c4, v);
        float4 vb = *(const float4*)(WkT + (size_t)(e0 + row) * E_SZ + h * 64 + c4 * 4);
        store_pair(sm, B_H_OFF, B_L_OFF, row, c4, vb);
    }
    __syncthreads();

    float acc[4][4] = {};
    mma_tile64_8w(sb, wm, wn, lane, acc);

    {
        int r0 = h * 64 + wm + (lane >> 2);
        #pragma unroll
        for (int ni = 0; ni < 4; ni++) {
            int c0 = e0 + wn + ni * 8 + (lane & 3) * 2;
            *(float2*)(T + (size_t)r0 * E_SZ + c0) = make_float2(acc[ni][0], acc[ni][1]);
            *(float2*)(T + (size_t)(r0 + 8) * E_SZ + c0) = make_float2(acc[ni][2], acc[ni][3]);
        }
    }
}

// ---------------------------------------------------------------
// Big NT GEMM body, CTA tile 128x64 (8 warps, warp tile 32x32)
// ---------------------------------------------------------------
#define BG_A_H 0
#define BG_A_L 18432
#define BG_B_H 36864
#define BG_B_L 46080
#define BG_SMEM 55296

__device__ __forceinline__ void big_nt_body(
    char* sm, int tid,
    const float* __restrict__ A, const float* __restrict__ B,
    float* __restrict__ PB, int bm, int bn, int z)
{
    const int wid = tid >> 5, lane = tid & 31;
    const int wm = (wid & 3) * 32, wn = (wid >> 2) * 32;
    const int kbase = z * 384;
    const uint32_t sb = smem_u32(sm);

    float acc[2][4][4] = {};
    float4 pa[8], pb[4];

    #pragma unroll
    for (int j = 0; j < 8; j++) {
        int fid = tid + j * 256;
        int row = fid >> 4, c4 = fid & 15;
        pa[j] = *(const float4*)(A + (size_t)(bm + row) * E_SZ + kbase + c4 * 4);
    }
    #pragma unroll
    for (int j = 0; j < 4; j++) {
        int fid = tid + j * 256;
        int row = fid >> 4, c4 = fid & 15;
        pb[j] = *(const float4*)(B + (size_t)(bn + row) * E_SZ + kbase + c4 * 4);
    }

    for (int it = 0; it < 6; it++) {
        #pragma unroll
        for (int j = 0; j < 8; j++) {
            int fid = tid + j * 256;
            int row = fid >> 4, c4 = fid & 15;
            store_pair(sm, BG_A_H, BG_A_L, row, c4, pa[j]);
        }
        #pragma unroll
        for (int j = 0; j < 4; j++) {
            int fid = tid + j * 256;
            int row = fid >> 4, c4 = fid & 15;
            store_pair(sm, BG_B_H, BG_B_L, row, c4, pb[j]);
        }
        __syncthreads();
        if (it + 1 < 6) {
            int k0 = kbase + (it + 1) * 64;
            #pragma unroll
            for (int j = 0; j < 8; j++) {
                int fid = tid + j * 256;
                int row = fid >> 4, c4 = fid & 15;
                pa[j] = *(const float4*)(A + (size_t)(bm + row) * E_SZ + k0 + c4 * 4);
            }
            #pragma unroll
            for (int j = 0; j < 4; j++) {
                int fid = tid + j * 256;
                int row = fid >> 4, c4 = fid & 15;
                pb[j] = *(const float4*)(B + (size_t)(bn + row) * E_SZ + k0 + c4 * 4);
            }
        }
        #pragma unroll
        for (int ks = 0; ks < 4; ks++) {
            uint32_t a_h[2][4], a_l[2][4], b_h[4][2], b_l[4][2];
            #pragma unroll
            for (int mi = 0; mi < 2; mi++) {
                uint32_t r  = wm + mi * 16 + (lane & 15);
                uint32_t cb = ks * 32 + ((lane >> 4) << 4);
                ldsm4(a_h[mi], sb + BG_A_H + r * PITCH + cb);
                ldsm4(a_l[mi], sb + BG_A_L + r * PITCH + cb);
            }
            #pragma unroll
            for (int g = 0; g < 2; g++) {
                uint32_t n  = wn + g * 16 + (lane & 7) + (((lane >> 4) & 1) << 3);
                uint32_t cb = ks * 32 + (((lane >> 3) & 1) << 4);
                uint32_t t[4];
                ldsm4(t, sb + BG_B_H + n * PITCH + cb);
                b_h[g*2][0] = t[0]; b_h[g*2][1] = t[1];
                b_h[g*2+1][0] = t[2]; b_h[g*2+1][1] = t[3];
                ldsm4(t, sb + BG_B_L + n * PITCH + cb);
                b_l[g*2][0] = t[0]; b_l[g*2][1] = t[1];
                b_l[g*2+1][0] = t[2]; b_l[g*2+1][1] = t[3];
            }
            #pragma unroll
            for (int mi = 0; mi < 2; mi++)
                #pragma unroll
                for (int ni = 0; ni < 4; ni++) {
                    mma16816(acc[mi][ni], a_h[mi], b_h[ni]);
                    mma16816(acc[mi][ni], a_h[mi], b_l[ni]);
                    mma16816(acc[mi][ni], a_l[mi], b_h[ni]);
                }
        }
        __syncthreads();
    }

    float* Cp = PB + (size_t)z * E_SZ * E_SZ;
    #pragma unroll
    for (int mi = 0; mi < 2; mi++) {
        int r0 = bm + wm + mi * 16 + (lane >> 2);
        #pragma unroll
        for (int ni = 0; ni < 4; ni++) {
            int c0 = bn + wn + ni * 8 + (lane & 3) * 2;
            *(float2*)(Cp + (size_t)r0 * E_SZ + c0) =
                make_float2(acc[mi][ni][0], acc[mi][ni][1]);
            *(float2*)(Cp + (size_t)(r0 + 8) * E_SZ + c0) =
                make_float2(acc[mi][ni][2], acc[mi][ni][3]);
        }
    }
}

// ---------------------------------------------------------------
// k3: gemm1 (144 flattened) | gather half 2 (1024)
// ---------------------------------------------------------------
#define K3_GEMM 144
#define K3_GRID (K3_GEMM + 1024)

__global__ __launch_bounds__(256)
void k3_gemm1_gather(const float* __restrict__ T,
                     const float* __restrict__ WsT,
                     float* __restrict__ PB,
                     const float* __restrict__ x,
                     const float* __restrict__ bc,
                     const float* __restrict__ off,
                     float* __restrict__ S)
{
    __shared__ __align__(16) char sm[BG_SMEM];
    const int bid = blockIdx.x;
    const int tid = threadIdx.x;

    if (bid >= K3_GEMM) {
        gather_point(1024 + (bid - K3_GEMM), tid, x, bc, off, S);
        return;
    }
    const int n = bid % 12;
    const int rest = bid / 12;
    const int m = rest % 6, z = rest / 6;
    big_nt_body(sm, tid, T, WsT, PB, m * 128, n * 64, z);
}

// ---------------------------------------------------------------
// Fused attention (R12 proven config): grid (64 b, 2 halves of 6), 512 thr.
// ---------------------------------------------------------------
#define HGRP 6
__global__ __launch_bounds__(512)
void attn_fuse_kernel(const float* __restrict__ QHp,
                      const float* __restrict__ S,
                      float* __restrict__ WS)
{
    extern __shared__ float smf[];
    float* Ssm = smf;
    float* qsm = smf + NB * E_SZ;
    float* sc  = qsm + HGRP * E_SZ;
    float* at  = sc + HGRP * NB;

    const int b  = blockIdx.x;
    const int h0 = blockIdx.y * HGRP;
    const int t  = threadIdx.x;
    const int w = t >> 5, lane = t & 31;

    {
        const float4* src = (const float4*)(S + (size_t)b * NB * E_SZ);
        float4* dst = (float4*)Ssm;
        #pragma unroll
        for (int i = t; i < NB * E_SZ / 4; i += 512) dst[i] = src[i];
        float4* qdst = (float4*)qsm;
        for (int i = t; i < HGRP * E_SZ / 4; i += 512) {
            int hl = i / 192, c4 = i - hl * 192;
            const float4* q0 = (const float4*)(QHp + (size_t)((h0 + hl) * 64 + b) * E_SZ) + c4;
            float4 v0 = *q0;
            float4 v1 = *(const float4*)((const float*)q0 + (size_t)E_SZ * E_SZ);
            v0.x += v1.x; v0.y += v1.y; v0.z += v1.z; v0.w += v1.w;
            qdst[i] = v0;
        }
    }
    __syncthreads();

    if (w < 12) {
        const int hp = w >> 2, pg = w & 3;
        const int ha = hp * 2, hb = ha + 1;
        float qa[24], qb[24];
        #pragma unroll
        for (int i = 0; i < 24; i++) {
            qa[i] = qsm[ha * E_SZ + lane + i * 32];
            qb[i] = qsm[hb * E_SZ + lane + i * 32];
        }
        #pragma unroll
        for (int p = 0; p < 8; p++) {
            const int pp = pg * 8 + p;
            const float* sr = Ssm + pp * E_SZ;
            float acca = 0.f, accb = 0.f;
            #pragma unroll
            for (int i = 0; i < 24; i++) {
                float sv = sr[lane + i * 32];
                acca = fmaf(qa[i], sv, acca);
                accb = fmaf(qb[i], sv, accb);
            }
            #pragma unroll
            for (int o = 16; o; o >>= 1) {
                acca += __shfl_xor_sync(0xffffffffu, acca, o);
                accb += __shfl_xor_sync(0xffffffffu, accb, o);
            }
            if (lane == 0) {
                sc[ha * 32 + pp] = acca * 0.125f;
                sc[hb * 32 + pp] = accb * 0.125f;
            }
        }
    }
    __syncthreads();

    if (w < HGRP) {
        float s = sc[w*32 + lane];
        float m = s;
        #pragma unroll
        for (int o = 16; o; o >>= 1) m = fmaxf(m, __shfl_xor_sync(0xffffffffu, m, o));
        float e = __expf(s - m);
        float sum = e;
        #pragma unroll
        for (int o = 16; o; o >>= 1) sum += __shfl_xor_sync(0xffffffffu, sum, o);
        at[w*32 + lane] = e / sum;
    }
    __syncthreads();

    if (w < 12) {
        const int hp = w >> 2, cg = w & 3;
        const int ha = hp * 2, hb = ha + 1;
        float ata[32], atb[32];
        #pragma unroll
        for (int p = 0; p < 32; p++) {
            ata[p] = at[ha * 32 + p];
            atb[p] = at[hb * 32 + p];
        }
        float* wrow_a = WS + (size_t)((h0 + ha) * 64 + b) * E_SZ;
        float* wrow_b = WS + (size_t)((h0 + hb) * 64 + b) * E_SZ;
        #pragma unroll
        for (int j = 0; j < 6; j++) {
            const int c = cg * 192 + j * 32 + lane;
            float acca = 0.f, accb = 0.f;
            #pragma unroll
            for (int p = 0; p < 32; p++) {
                float sv = Ssm[p * E_SZ + c];
                acca = fmaf(ata[p], sv, acca);
                accb = fmaf(atb[p], sv, accb);
            }
            wrow_a[c] = acca;
            wrow_b[c] = accb;
        }
    }
}

// ---------------------------------------------------------------
// grid barrier (all CTAs resident by construction: grid <= 148)
// ---------------------------------------------------------------
__device__ __forceinline__ void grid_barrier(int expected) {
    __threadfence();
    __syncthreads();
    if (threadIdx.x == 0) {
        int gen = *((volatile int*)&g_bar_gen);
        int v = atomicAdd(&g_bar_count, 1);
        if (v == expected - 1) {
            g_bar_count = 0;
            __threadfence();
            *((volatile int*)&g_bar_gen) = gen + 1;
        } else {
            while (*((volatile int*)&g_bar_gen) == gen) { }
            __threadfence();
        }
    }
    __syncthreads();
}

// ---------------------------------------------------------------
// tail_fused: gemm2 (144) -> barrier -> ctx (48) -> barrier -> outproj (48)
// grid 144, 256 thr, 55KB static smem. All CTAs resident.
// ---------------------------------------------------------------
__global__ __launch_bounds__(256)
void tail_fused(const float* __restrict__ WS,
                const float* __restrict__ sample_w,
                const float* __restrict__ sample_b,
                const float* __restrict__ in_proj_w,
                const float* __restrict__ in_proj_b,
                const float* __restrict__ Wo,
                float* __restrict__ PB,
                float* __restrict__ P2,
                float* __restrict__ P1)
{
    __shared__ __align__(16) char sm[BG_SMEM];
    const int bid = blockIdx.x;
    const int tid = threadIdx.x;
    const int wid = tid >> 5, lane = tid & 31;
    const uint32_t sb = smem_u32(sm);

    // ---- phase A: gemm2 (U partials = WS @ Ws^T, K-split 2) ----
    {
        const int n = bid % 12;
        const int rest = bid / 12;
        const int m = rest % 6, z = rest / 6;
        big_nt_body(sm, tid, WS, sample_w, PB, m * 128, n * 64, z);
    }
    grid_barrier(144);

    // ---- phase B: ctx partials (48 CTAs) ----
    if (bid < 48) {
        const int h = bid % 12, s = bid / 12;
        const int wm = (wid & 3) * 16, wn = (wid >> 2) * 32;
        const float* B = in_proj_w + (size_t)(2 * E_SZ + h * 64) * E_SZ;

        float acc[4][4] = {};
        for (int it = 0; it < 3; it++) {
            int k0 = s * 192 + it * 64;
            #pragma unroll
            for (int j = 0; j < 4; j++) {
                int fid = tid + j * 256;
                int row = fid >> 4, c4 = fid & 15;
                const float* a0 = PB + (size_t)(h * 64 + row) * E_SZ + k0 + c4 * 4;
                float4 va = *(const float4*)a0;
                float4 v1 = *(const float4*)(a0 + (size_t)E_SZ * E_SZ);
                float4 bs = *(const float4*)(sample_b + k0 + c4 * 4);
                va.x += v1.x + bs.x; va.y += v1.y + bs.y;
                va.z += v1.z + bs.z; va.w += v1.w + bs.w;
                store_pair(sm, A_H_OFF, A_L_OFF, row, c4, va);
                float4 vb = *(const float4*)(B + (size_t)row * E_SZ + k0 + c4 * 4);
                store_pair(sm, B_H_OFF, B_L_OFF, row, c4, vb);
            }
            __syncthreads();
            mma_tile64_8w(sb, wm, wn, lane, acc);
            __syncthreads();
        }
        float* Pp = P2 + (size_t)(h * 4 + s) * 4096;
        int r0 = wm + (lane >> 2);
        #pragma unroll
        for (int ni = 0; ni < 4; ni++) {
            int c0 = wn + ni * 8 + (lane & 3) * 2;
            *(float2*)(Pp + r0 * 64 + c0) = make_float2(acc[ni][0], acc[ni][1]);
            *(float2*)(Pp + (r0 + 8) * 64 + c0) = make_float2(acc[ni][2], acc[ni][3]);
        }
    }
    grid_barrier(144);

    // ---- phase C: out-proj partials (48 CTAs) ----
    if (bid < 48) {
        const int bn = (bid % 12) * 64, s = bid / 12;
        const int wm = (wid & 3) * 16, wn = (wid >> 2) * 32;

        float acc[4][4] = {};
        for (int it = 0; it < 3; it++) {
            int k0 = s * 192 + it * 64;
            int hh = k0 >> 6;
            #pragma unroll
            for (int j = 0; j < 4; j++) {
                int fid = tid + j * 256;
                int row = fid >> 4, c4 = fid & 15;
                const float* pbase = P2 + (size_t)(hh * 4) * 4096 + row * 64 + c4 * 4;
                float4 v = *(const float4*)pbase;
                #pragma unroll
                for (int ss = 1; ss < 4; ss++) {
                    float4 p = *(const float4*)(pbase + (size_t)ss * 4096);
                    v.x += p.x; v.y += p.y; v.z += p.z; v.w += p.w;
                }
                float4 bv = *(const float4*)(in_proj_b + 2 * E_SZ + k0 + c4 * 4);
                v.x += bv.x; v.y += bv.y; v.z += bv.z; v.w += bv.w;
                store_pair(sm, A_H_OFF, A_L_OFF, row, c4, v);
                float4 vb = *(const float4*)(Wo + (size_t)(bn + row) * E_SZ + k0 + c4 * 4);
                store_pair(sm, B_H_OFF, B_L_OFF, row, c4, vb);
            }
            __syncthreads();
            mma_tile64_8w(sb, wm, wn, lane, acc);
            __syncthreads();
        }
        float* Pp = P1 + (size_t)s * B_SZ * E_SZ;
        int r0 = wm + (lane >> 2);
        #pragma unroll
        for (int ni = 0; ni < 4; ni++) {
            int c0 = bn + wn + ni * 8 + (lane & 3) * 2;
            *(float2*)(Pp + (size_t)r0 * E_SZ + c0) = make_float2(acc[ni][0], acc[ni][1]);
            *(float2*)(Pp + (size_t)(r0 + 8) * E_SZ + c0) = make_float2(acc[ni][2], acc[ni][3]);
        }
    }
}

// ---------------------------------------------------------------
// Fused reduce + broadcast
// ---------------------------------------------------------------
__global__ __launch_bounds__(256)
void bcast_reduce_kernel(const float* __restrict__ P1,
                         const float* __restrict__ bo,
                         const float* __restrict__ conf,
                         float* __restrict__ out)
{
    __shared__ __align__(16) float ao[E_SZ];
    const int b  = blockIdx.x;
    const int n0 = blockIdx.y * 27;
    const int t  = threadIdx.x;
    const float cf = conf[b];

    for (int c = t; c < E_SZ; c += 256) {
        float a0 = P1[(size_t)b * E_SZ + c];
        float a1 = P1[(size_t)(B_SZ + b) * E_SZ + c];
        float a2 = P1[(size_t)(2 * B_SZ + b) * E_SZ + c];
        float a3 = P1[(size_t)(3 * B_SZ + b) * E_SZ + c];
        ao[c] = ((a0 + a1) + (a2 + a3) + bo[c]) * cf;
    }
    __syncthreads();

    const float4* src = (const float4*)ao;
    float4* dstb = (float4*)(out + ((size_t)b * FULLN + n0) * E_SZ);
    const int nrows = min(27, FULLN - n0);
    for (int i = t; i < nrows * 192; i += 256) {
        int r = i / 192, c = i - r * 192;
        dstb[(size_t)r * 192 + c] = src[c];
    }
}

// ---------------------------------------------------------------
extern "C" void kernel_launch(void* const* d_in, const int* in_sizes, int n_in,
                              void* d_out, int out_size)
{
    const float* x           = (const float*)d_in[0];
    const float* bio_embed   = (const float*)d_in[1];
    const float* base_coords = (const float*)d_in[2];
    const float* offsets     = (const float*)d_in[3];
    const float* confidence  = (const float*)d_in[4];
    const float* sample_w    = (const float*)d_in[5];
    const float* sample_b    = (const float*)d_in[6];
    const float* in_proj_w   = (const float*)d_in[7];
    const float* in_proj_b   = (const float*)d_in[8];
    const float* out_proj_w  = (const float*)d_in[9];
    const float* out_proj_b  = (const float*)d_in[10];
    float* out = (float*)d_out;

    float *S, *T, *WS, *P1, *P2, *PB, *WsT, *WkT;
    cudaGetSymbolAddress((void**)&S,   g_S);
    cudaGetSymbolAddress((void**)&T,   g_T);
    cudaGetSymbolAddress((void**)&WS,  g_WS);
    cudaGetSymbolAddress((void**)&P1,  g_P1);
    cudaGetSymbolAddress((void**)&P2,  g_P2);
    cudaGetSymbolAddress((void**)&PB,  g_PB);
    cudaGetSymbolAddress((void**)&WsT, g_WsT);
    cudaGetSymbolAddress((void**)&WkT, g_WkT);

    const int attn_smem = (NB * E_SZ + HGRP * E_SZ + 2 * HGRP * NB) * sizeof(float);
    cudaFuncSetAttribute(attn_fuse_kernel,
                         cudaFuncAttributeMaxDynamicSharedMemorySize, attn_smem);

    // 1) qproj partials + both transposes
    k1_front<<<K1_GRID, 256>>>(bio_embed, in_proj_w, sample_w, P1, WsT, WkT);

    // 2) thead + gather half 1 (overlapped)
    k2_thead_gather<<<K2_GRID, 256>>>(P1, in_proj_b, WkT, T,
                                      x, base_coords, offsets, S);

    // 3) QH partials = T @ Ws (K-split 2) + gather half 2 (overlapped)
    k3_gemm1_gather<<<K3_GRID, 256>>>(T, WsT, PB,
                                      x, base_coords, offsets, S);

    // 4) fused scores (sums QH partials) + softmax + weighted-S
    attn_fuse_kernel<<<dim3(B_SZ, 2), 512, attn_smem>>>(PB, S, WS);

    // 5) tail: gemm2 -> ctx -> outproj, one launch with grid barriers
    tail_fused<<<144, 256>>>(WS, sample_w, sample_b, in_proj_w, in_proj_b,
                             out_proj_w, PB, P2, P1);

    // 6) fused reduce + broadcast * confidence
    bcast_reduce_kernel<<<dim3(B_SZ, 19), 256>>>(P1, out_proj_b, confidence, out);
}